// round 13
// baseline (speedup 1.0000x reference)
#include <cuda_runtime.h>
#include <cuda_bf16.h>
#include <cuda_fp16.h>
#include <math.h>
#include <stdint.h>

#define D_MODEL 2048
#define T_SEQ   2048
#define NQH     32
#define NKVH    8
#define HD      64
#define DIM_KV  512
#define KDIM    2048
#define KA2     (2*KDIM)       // fp16 2-term A width = 4096
#define PADH    72             // GEMM smem row stride (halves)
#define QPAD    136            // flash Q smem row stride (halves)
#define KVPAD   72             // flash K/V smem row stride (halves)

// ---------------------------------------------------------------------------
// Device-global scratch
// ---------------------------------------------------------------------------
__device__ __align__(16) __half g_A2q[T_SEQ * KA2];
__device__ __align__(16) __half g_A2k[T_SEQ * KA2];
__device__ __align__(16) __half g_A2v[T_SEQ * KA2];
__device__ __align__(16) __half g_A2o[T_SEQ * KA2];      // flash output [Oh|Ol]
__device__ __align__(16) __half g_B2q[D_MODEL * KDIM];
__device__ __align__(16) __half g_B2k[DIM_KV  * KDIM];
__device__ __align__(16) __half g_B2v[DIM_KV  * KDIM];
__device__ __align__(16) __half g_B2o[D_MODEL * KDIM];
__device__ __align__(16) __half g_Q2[NQH  * T_SEQ * 128]; // [h][t][Qh|Ql]
__device__ __align__(16) __half g_K2h[NKVH * T_SEQ * 64]; // [kvh][t][Kh]
__device__ __align__(16) __half g_Vth[DIM_KV * T_SEQ];    // V^T hi [d][t]
__device__ float g_rc[T_SEQ * 32];
__device__ float g_rs[T_SEQ * 32];

// ---------------------------------------------------------------------------
// PTX helpers
// ---------------------------------------------------------------------------
__device__ __forceinline__ uint32_t smem_u32(const void* p) {
    uint32_t a;
    asm("{ .reg .u64 t; cvta.to.shared.u64 t, %1; cvt.u32.u64 %0, t; }"
        : "=r"(a) : "l"(p));
    return a;
}

__device__ __forceinline__ void ldmatrix_x4(uint32_t& r0, uint32_t& r1,
                                            uint32_t& r2, uint32_t& r3,
                                            uint32_t addr) {
    asm volatile("ldmatrix.sync.aligned.m8n8.x4.shared.b16 {%0,%1,%2,%3}, [%4];"
                 : "=r"(r0), "=r"(r1), "=r"(r2), "=r"(r3) : "r"(addr));
}

__device__ __forceinline__ void mma16816(float* d, const uint32_t* a,
                                         uint32_t b0, uint32_t b1) {
    asm volatile(
        "mma.sync.aligned.m16n8k16.row.col.f32.f16.f16.f32 "
        "{%0,%1,%2,%3}, {%4,%5,%6,%7}, {%8,%9}, {%0,%1,%2,%3};"
        : "+f"(d[0]), "+f"(d[1]), "+f"(d[2]), "+f"(d[3])
        : "r"(a[0]), "r"(a[1]), "r"(a[2]), "r"(a[3]), "r"(b0), "r"(b1));
}

__device__ __forceinline__ void cp_async16(uint32_t saddr, const void* gaddr) {
    asm volatile("cp.async.cg.shared.global [%0], [%1], 16;"
                 :: "r"(saddr), "l"(gaddr));
}
#define CP_COMMIT() asm volatile("cp.async.commit_group;" ::: "memory")
#define CP_WAIT(n)  asm volatile("cp.async.wait_group %0;" :: "n"(n) : "memory")

__device__ __forceinline__ uint32_t pack_h2(__half a, __half b) {
    return ((uint32_t)__half_as_ushort(b) << 16) | __half_as_ushort(a);
}

// ---------------------------------------------------------------------------
// Conversions (merged launches)
// ---------------------------------------------------------------------------
__global__ void split_a3_kernel(const float* __restrict__ Xq,
                                const float* __restrict__ Xk,
                                const float* __restrict__ Xv,
                                __half* __restrict__ A2q,
                                __half* __restrict__ A2k,
                                __half* __restrict__ A2v)
{
    const float* X = (blockIdx.z == 0) ? Xq : (blockIdx.z == 1) ? Xk : Xv;
    __half* A2     = (blockIdx.z == 0) ? A2q : (blockIdx.z == 1) ? A2k : A2v;
    int idx = blockIdx.x * blockDim.x + threadIdx.x;
    if (idx >= T_SEQ * KDIM) return;
    int m = idx / KDIM, k = idx % KDIM;
    float x = X[idx];
    __half h = __float2half(x);
    __half l = __float2half(x - __half2float(h));
    size_t b = (size_t)m * KA2;
    A2[b + k]        = h;
    A2[b + KDIM + k] = l;
}

__global__ void split_b4_kernel(const float* __restrict__ Wq,
                                const float* __restrict__ Wk,
                                const float* __restrict__ Wv,
                                const float* __restrict__ Wo,
                                __half* __restrict__ B2q,
                                __half* __restrict__ B2k,
                                __half* __restrict__ B2v,
                                __half* __restrict__ B2o)
{
    const int z = blockIdx.z;
    const float* W = (z == 0) ? Wq : (z == 1) ? Wk : (z == 2) ? Wv : Wo;
    __half* B2     = (z == 0) ? B2q : (z == 1) ? B2k : (z == 2) ? B2v : B2o;
    const int N    = (z == 1 || z == 2) ? DIM_KV : D_MODEL;

    __shared__ float tile[32][33];
    int n0 = blockIdx.x * 32, k0 = blockIdx.y * 32;
    if (n0 >= N) return;
    int tx = threadIdx.x, ty = threadIdx.y;
    #pragma unroll
    for (int i = 0; i < 32; i += 8)
        tile[ty + i][tx] = W[(size_t)(k0 + ty + i) * N + n0 + tx];
    __syncthreads();
    #pragma unroll
    for (int i = 0; i < 32; i += 8) {
        int n = n0 + ty + i;
        B2[(size_t)n * KDIM + k0 + tx] = __float2half(tile[tx][ty + i]);
    }
}

__global__ void rope_table_kernel(float* __restrict__ rc, float* __restrict__ rs)
{
    int idx = blockIdx.x * blockDim.x + threadIdx.x;
    if (idx >= T_SEQ * 32) return;
    int t = idx >> 5, i = idx & 31;
    float invf = (float)pow(500000.0, -(double)i / 32.0);
    float angf = (float)t * invf;
    double ang = (double)angf;
    rc[idx] = (float)cos(ang);
    rs[idx] = (float)sin(ang);
}

// ---------------------------------------------------------------------------
// Shared GEMM mainloop (CTA 128x128, 128 threads, 4 warps 64x64, DB cp.async)
// ---------------------------------------------------------------------------
#define GEMM_SMEM_BYTES (4 * 128 * PADH * 2)   // 73728

__device__ __forceinline__ void ldgsts_tileS(uint32_t sBase, const __half* G,
                                             int k0, int tid, int strideH)
{
    #pragma unroll
    for (int i = 0; i < 8; i++) {
        int id  = tid + (i << 7);
        int row = id >> 3;
        int c8  = id & 7;
        cp_async16(sBase + (uint32_t)(row * PADH + c8 * 8) * 2,
                   G + (size_t)row * strideH + k0 + c8 * 8);
    }
}

__device__ __forceinline__ void gemm_mainloop(
    uint32_t shBase, const __half* Ag, const __half* Bg,
    int tid, int lane, int wm, int wn, float acc[4][8][4])
{
    const uint32_t TILE_B = 128 * PADH * 2;
    const int nCh = KA2 / 64;   // 64

    ldgsts_tileS(shBase + 0 * TILE_B, Ag, 0, tid, KA2);
    ldgsts_tileS(shBase + 2 * TILE_B, Bg, 0, tid, KDIM);
    CP_COMMIT();

    const int lrow = (lane & 7) + ((lane >> 3) & 1) * 8;
    const int lcol = (lane >> 4) * 8;

    for (int c = 0; c < nCh; c++) {
        const int s = c & 1;
        if (c + 1 < nCh) {
            const int s2 = s ^ 1;
            ldgsts_tileS(shBase + s2 * TILE_B,       Ag, (c + 1) * 64, tid, KA2);
            ldgsts_tileS(shBase + (2 + s2) * TILE_B, Bg, (((c + 1) & 31)) * 64, tid, KDIM);
            CP_COMMIT();
            CP_WAIT(1);
        } else {
            CP_WAIT(0);
        }
        __syncthreads();

        const uint32_t aB = shBase + s * TILE_B;
        const uint32_t bB = shBase + (2 + s) * TILE_B;
        #pragma unroll
        for (int ks = 0; ks < 4; ks++) {
            const int k16 = ks * 16;
            uint32_t af[4][4], bfr[4][4];
            #pragma unroll
            for (int fm = 0; fm < 4; fm++)
                ldmatrix_x4(af[fm][0], af[fm][1], af[fm][2], af[fm][3],
                    aB + (uint32_t)((wm * 64 + fm * 16 + lrow) * PADH + k16 + lcol) * 2);
            #pragma unroll
            for (int fp = 0; fp < 4; fp++)
                ldmatrix_x4(bfr[fp][0], bfr[fp][1], bfr[fp][2], bfr[fp][3],
                    bB + (uint32_t)((wn * 64 + fp * 16 + lrow) * PADH + k16 + lcol) * 2);
            #pragma unroll
            for (int fm = 0; fm < 4; fm++)
                #pragma unroll
                for (int fn = 0; fn < 8; fn++) {
                    uint32_t b0 = (fn & 1) ? bfr[fn >> 1][1] : bfr[fn >> 1][0];
                    uint32_t b1 = (fn & 1) ? bfr[fn >> 1][3] : bfr[fn >> 1][2];
                    mma16816(acc[fm][fn], af[fm], b0, b1);
                }
        }
        __syncthreads();
    }
}

// ---------------------------------------------------------------------------
// Uber projection kernel: one launch computes Q (256 CTAs), K (64), V (64).
//   bid <  256: Q tile -> rope + 2-term split -> Q2
//   bid < 320 : K tile -> rope -> K2h
//   else      : V tile -> Vth (transposed hi)
// ---------------------------------------------------------------------------
__global__ __launch_bounds__(128, 2) void gemm_uber_kernel(
    const __half* __restrict__ A2q, const __half* __restrict__ B2q,
    const __half* __restrict__ A2k, const __half* __restrict__ B2k,
    const __half* __restrict__ A2v, const __half* __restrict__ B2v,
    __half* __restrict__ Q2, __half* __restrict__ K2h, __half* __restrict__ Vth,
    const float* __restrict__ rc, const float* __restrict__ rs)
{
    extern __shared__ __half sh[];
    uint32_t shBase = smem_u32(sh);
    const int tid  = threadIdx.x;
    const int lane = tid & 31;
    const int wid  = tid >> 5;
    const int wm   = wid & 1;
    const int wn   = wid >> 1;

    const int bid = blockIdx.x;
    int mode, rowBase, colBase;
    const __half *Ap, *Bp;
    if (bid < 256) {          // Q: 16x16 tiles
        mode = 0;
        rowBase = (bid >> 4) * 128;
        colBase = (bid & 15) * 128;
        Ap = A2q; Bp = B2q;
    } else if (bid < 320) {   // K: 16x4 tiles
        mode = 1;
        int b = bid - 256;
        rowBase = (b >> 2) * 128;
        colBase = (b & 3) * 128;
        Ap = A2k; Bp = B2k;
    } else {                  // V
        mode = 2;
        int b = bid - 320;
        rowBase = (b >> 2) * 128;
        colBase = (b & 3) * 128;
        Ap = A2v; Bp = B2v;
    }

    float acc[4][8][4];
    #pragma unroll
    for (int i = 0; i < 4; i++)
        #pragma unroll
        for (int j = 0; j < 8; j++)
            #pragma unroll
            for (int q = 0; q < 4; q++) acc[i][j][q] = 0.0f;

    gemm_mainloop(shBase, Ap + (size_t)rowBase * KA2, Bp + (size_t)colBase * KDIM,
                  tid, lane, wm, wn, acc);

    #pragma unroll
    for (int fm = 0; fm < 4; fm++) {
        #pragma unroll
        for (int fn = 0; fn < 8; fn++) {
            int r0 = rowBase + wm * 64 + fm * 16 + (lane >> 2);
            int c0 = colBase + wn * 64 + fn * 8 + (lane & 3) * 2;
            float a0 = acc[fm][fn][0], a1 = acc[fm][fn][1];
            float a2 = acc[fm][fn][2], a3 = acc[fm][fn][3];
            if (mode == 2) {
                Vth[(size_t)c0 * T_SEQ + r0]           = __float2half(a0);
                Vth[(size_t)(c0 + 1) * T_SEQ + r0]     = __float2half(a1);
                Vth[(size_t)c0 * T_SEQ + r0 + 8]       = __float2half(a2);
                Vth[(size_t)(c0 + 1) * T_SEQ + r0 + 8] = __float2half(a3);
            } else {
                const int h = c0 >> 6;
                const int d = c0 & 63;
                const int i = d >> 1;
                float c1 = rc[r0 * 32 + i],       s1 = rs[r0 * 32 + i];
                float c2 = rc[(r0 + 8) * 32 + i], s2 = rs[(r0 + 8) * 32 + i];
                float y0 = a0 * c1 - a1 * s1, y1 = a0 * s1 + a1 * c1;
                float y2 = a2 * c2 - a3 * s2, y3 = a2 * s2 + a3 * c2;
                __half h0 = __float2half(y0), h1 = __float2half(y1);
                __half h2 = __float2half(y2), h3 = __float2half(y3);
                if (mode == 0) {
                    size_t b0 = ((size_t)h * T_SEQ + r0) * 128 + d;
                    size_t b8 = b0 + 8 * 128;
                    *reinterpret_cast<uint32_t*>(Q2 + b0) = pack_h2(h0, h1);
                    *reinterpret_cast<uint32_t*>(Q2 + b8) = pack_h2(h2, h3);
                    *reinterpret_cast<uint32_t*>(Q2 + b0 + 64) = pack_h2(
                        __float2half(y0 - __half2float(h0)),
                        __float2half(y1 - __half2float(h1)));
                    *reinterpret_cast<uint32_t*>(Q2 + b8 + 64) = pack_h2(
                        __float2half(y2 - __half2float(h2)),
                        __float2half(y3 - __half2float(h3)));
                } else {
                    size_t b0 = ((size_t)h * T_SEQ + r0) * 64 + d;
                    size_t b8 = b0 + 8 * 64;
                    *reinterpret_cast<uint32_t*>(K2h + b0) = pack_h2(h0, h1);
                    *reinterpret_cast<uint32_t*>(K2h + b8) = pack_h2(h2, h3);
                }
            }
        }
    }
}

// O-projection GEMM (mode 0 fp32 store)
__global__ __launch_bounds__(128, 2) void gemm_o_kernel(
    const __half* __restrict__ A2, const __half* __restrict__ B2,
    float* __restrict__ C)
{
    extern __shared__ __half sh[];
    uint32_t shBase = smem_u32(sh);
    const int tid  = threadIdx.x;
    const int lane = tid & 31;
    const int wid  = tid >> 5;
    const int wm   = wid & 1;
    const int wn   = wid >> 1;
    const int rowBase = blockIdx.y * 128;
    const int colBase = blockIdx.x * 128;

    float acc[4][8][4];
    #pragma unroll
    for (int i = 0; i < 4; i++)
        #pragma unroll
        for (int j = 0; j < 8; j++)
            #pragma unroll
            for (int q = 0; q < 4; q++) acc[i][j][q] = 0.0f;

    gemm_mainloop(shBase, A2 + (size_t)rowBase * KA2, B2 + (size_t)colBase * KDIM,
                  tid, lane, wm, wn, acc);

    #pragma unroll
    for (int fm = 0; fm < 4; fm++) {
        #pragma unroll
        for (int fn = 0; fn < 8; fn++) {
            int r0 = rowBase + wm * 64 + fm * 16 + (lane >> 2);
            int c0 = colBase + wn * 64 + fn * 8 + (lane & 3) * 2;
            *reinterpret_cast<float2*>(&C[(size_t)r0 * D_MODEL + c0]) =
                make_float2(acc[fm][fn][0], acc[fm][fn][1]);
            *reinterpret_cast<float2*>(&C[(size_t)(r0 + 8) * D_MODEL + c0]) =
                make_float2(acc[fm][fn][2], acc[fm][fn][3]);
        }
    }
}

// ---------------------------------------------------------------------------
// HMMA flash attention: 256 threads (8 warps), q-tile 256 rows x 1 head.
// 2 warps/SMSP -> MUFU(exp) overlaps HMMA across warps; K/V reuse x2.
// ---------------------------------------------------------------------------
#define FLASH_SMEM_BYTES ((256 * QPAD + 2 * 64 * KVPAD) * 2)   // 88064

__global__ __launch_bounds__(256, 1) void flash_hmma_kernel(
    const __half* __restrict__ Q2,
    const __half* __restrict__ K2h,
    const __half* __restrict__ Vth,
    __half* __restrict__ A2o)
{
    extern __shared__ __half fs[];
    const uint32_t QsA = smem_u32(fs);
    const uint32_t KsA = QsA + 256 * QPAD * 2;
    const uint32_t VsA = KsA + 64 * KVPAD * 2;

    const int tid = threadIdx.x, lane = tid & 31, wq = tid >> 5;  // wq 0..7
    const int h = blockIdx.y, kvh = h >> 2;
    const int m0 = (gridDim.x - 1 - (int)blockIdx.x) * 256;

    const int g  = lane >> 2;
    const int tg = lane & 3;
    const int lrow = (lane & 7) + ((lane >> 3) & 1) * 8;
    const int lcol = (lane >> 4) * 8;
    const float NEG = -1e30f;
    const float scale = 0.125f;

    {   // Q tile: 256 rows x 128 halves
        const __half* Qg = Q2 + ((size_t)h * T_SEQ + m0) * 128;
        #pragma unroll
        for (int u = 0; u < 16; u++) {
            int id = tid + u * 256;
            int row = id >> 4, c = id & 15;
            cp_async16(QsA + (uint32_t)(row * QPAD + c * 8) * 2,
                       Qg + (size_t)row * 128 + c * 8);
        }
        CP_COMMIT();
    }

    float o[2][8][4];
    #pragma unroll
    for (int i = 0; i < 2; i++)
        #pragma unroll
        for (int j = 0; j < 8; j++)
            #pragma unroll
            for (int q = 0; q < 4; q++) o[i][j][q] = 0.0f;
    float mrow[2][2] = {{NEG, NEG}, {NEG, NEG}};
    float lacc[2][2] = {{0.f, 0.f}, {0.f, 0.f}};

    const int nT = m0 / 64 + 4;
    for (int jt = 0; jt < nT; jt++) {
        const int j0 = jt * 64;
        __syncthreads();
        #pragma unroll
        for (int u = 0; u < 2; u++) {   // K tile: 64 x 64 halves
            int id = tid + u * 256;
            int row = id >> 3, c = id & 7;
            cp_async16(KsA + (uint32_t)(row * KVPAD + c * 8) * 2,
                       K2h + ((size_t)kvh * T_SEQ + j0 + row) * 64 + c * 8);
        }
        #pragma unroll
        for (int u = 0; u < 2; u++) {   // V tile
            int id = tid + u * 256;
            int row = id >> 3, c = id & 7;
            cp_async16(VsA + (uint32_t)(row * KVPAD + c * 8) * 2,
                       Vth + (size_t)(kvh * 64 + row) * T_SEQ + j0 + c * 8);
        }
        CP_COMMIT();
        CP_WAIT(0);
        __syncthreads();

        float s[2][8][4];
        #pragma unroll
        for (int i = 0; i < 2; i++)
            #pragma unroll
            for (int j = 0; j < 8; j++)
                #pragma unroll
                for (int q = 0; q < 4; q++) s[i][j][q] = 0.0f;

        #pragma unroll
        for (int kc = 0; kc < 8; kc++) {
            uint32_t af[2][4], bk[4][4];
            #pragma unroll
            for (int fm = 0; fm < 2; fm++)
                ldmatrix_x4(af[fm][0], af[fm][1], af[fm][2], af[fm][3],
                    QsA + (uint32_t)((wq * 32 + fm * 16 + lrow) * QPAD + kc * 16 + lcol) * 2);
            #pragma unroll
            for (int fp = 0; fp < 4; fp++)
                ldmatrix_x4(bk[fp][0], bk[fp][1], bk[fp][2], bk[fp][3],
                    KsA + (uint32_t)((fp * 16 + lrow) * KVPAD + (kc & 3) * 16 + lcol) * 2);
            #pragma unroll
            for (int fm = 0; fm < 2; fm++)
                #pragma unroll
                for (int fn = 0; fn < 8; fn++) {
                    uint32_t b0 = (fn & 1) ? bk[fn >> 1][1] : bk[fn >> 1][0];
                    uint32_t b1 = (fn & 1) ? bk[fn >> 1][3] : bk[fn >> 1][2];
                    mma16816(s[fm][fn], af[fm], b0, b1);
                }
        }

        #pragma unroll
        for (int fm = 0; fm < 2; fm++) {
            const int r0 = m0 + wq * 32 + fm * 16 + g;
            const int r1 = r0 + 8;
            float mx0 = NEG, mx1 = NEG;
            #pragma unroll
            for (int fn = 0; fn < 8; fn++) {
                const int cb = j0 + fn * 8 + tg * 2;
                float v0 = (cb     <= r0) ? s[fm][fn][0] * scale : NEG;
                float v1 = (cb + 1 <= r0) ? s[fm][fn][1] * scale : NEG;
                float v2 = (cb     <= r1) ? s[fm][fn][2] * scale : NEG;
                float v3 = (cb + 1 <= r1) ? s[fm][fn][3] * scale : NEG;
                s[fm][fn][0] = v0; s[fm][fn][1] = v1;
                s[fm][fn][2] = v2; s[fm][fn][3] = v3;
                mx0 = fmaxf(mx0, fmaxf(v0, v1));
                mx1 = fmaxf(mx1, fmaxf(v2, v3));
            }
            mx0 = fmaxf(mx0, __shfl_xor_sync(0xffffffffu, mx0, 1));
            mx0 = fmaxf(mx0, __shfl_xor_sync(0xffffffffu, mx0, 2));
            mx1 = fmaxf(mx1, __shfl_xor_sync(0xffffffffu, mx1, 1));
            mx1 = fmaxf(mx1, __shfl_xor_sync(0xffffffffu, mx1, 2));
            const float mn0 = fmaxf(mrow[fm][0], mx0);
            const float mn1 = fmaxf(mrow[fm][1], mx1);
            const float c0 = __expf(mrow[fm][0] - mn0);
            const float c1 = __expf(mrow[fm][1] - mn1);
            mrow[fm][0] = mn0; mrow[fm][1] = mn1;
            float ls0 = 0.f, ls1 = 0.f;
            #pragma unroll
            for (int fn = 0; fn < 8; fn++) {
                float p0 = __expf(s[fm][fn][0] - mn0);
                float p1 = __expf(s[fm][fn][1] - mn0);
                float p2 = __expf(s[fm][fn][2] - mn1);
                float p3 = __expf(s[fm][fn][3] - mn1);
                s[fm][fn][0] = p0; s[fm][fn][1] = p1;
                s[fm][fn][2] = p2; s[fm][fn][3] = p3;
                ls0 += p0 + p1; ls1 += p2 + p3;
                o[fm][fn][0] *= c0; o[fm][fn][1] *= c0;
                o[fm][fn][2] *= c1; o[fm][fn][3] *= c1;
            }
            lacc[fm][0] = lacc[fm][0] * c0 + ls0;
            lacc[fm][1] = lacc[fm][1] * c1 + ls1;
        }

        #pragma unroll
        for (int kc2 = 0; kc2 < 4; kc2++) {
            uint32_t aPh[2][4], aPl[2][4];
            #pragma unroll
            for (int fm = 0; fm < 2; fm++) {
                #pragma unroll
                for (int half = 0; half < 2; half++) {
                    const int fr = 2 * kc2 + half;
                    float p0 = s[fm][fr][0], p1 = s[fm][fr][1];
                    float p2 = s[fm][fr][2], p3 = s[fm][fr][3];
                    __half h0 = __float2half(p0), h1 = __float2half(p1);
                    __half h2 = __float2half(p2), h3 = __float2half(p3);
                    aPh[fm][half * 2 + 0] = pack_h2(h0, h1);
                    aPh[fm][half * 2 + 1] = pack_h2(h2, h3);
                    aPl[fm][half * 2 + 0] = pack_h2(
                        __float2half(p0 - __half2float(h0)),
                        __float2half(p1 - __half2float(h1)));
                    aPl[fm][half * 2 + 1] = pack_h2(
                        __float2half(p2 - __half2float(h2)),
                        __float2half(p3 - __half2float(h3)));
                }
            }
            uint32_t bv[4][4];
            #pragma unroll
            for (int fp = 0; fp < 4; fp++)
                ldmatrix_x4(bv[fp][0], bv[fp][1], bv[fp][2], bv[fp][3],
                    VsA + (uint32_t)((fp * 16 + lrow) * KVPAD + kc2 * 16 + lcol) * 2);
            #pragma unroll
            for (int fm = 0; fm < 2; fm++)
                #pragma unroll
                for (int fn = 0; fn < 8; fn++) {
                    uint32_t b0 = (fn & 1) ? bv[fn >> 1][1] : bv[fn >> 1][0];
                    uint32_t b1 = (fn & 1) ? bv[fn >> 1][3] : bv[fn >> 1][2];
                    mma16816(o[fm][fn], aPh[fm], b0, b1);
                    mma16816(o[fm][fn], aPl[fm], b0, b1);
                }
        }
    }

    float linv[2][2];
    #pragma unroll
    for (int fm = 0; fm < 2; fm++)
        #pragma unroll
        for (int half = 0; half < 2; half++) {
            float lv = lacc[fm][half];
            lv += __shfl_xor_sync(0xffffffffu, lv, 1);
            lv += __shfl_xor_sync(0xffffffffu, lv, 2);
            linv[fm][half] = 1.0f / lv;
        }
    #pragma unroll
    for (int fm = 0; fm < 2; fm++) {
        const int r0 = m0 + wq * 32 + fm * 16 + g;
        #pragma unroll
        for (int fn = 0; fn < 8; fn++) {
            const int col = h * HD + fn * 8 + tg * 2;
            float y0 = o[fm][fn][0] * linv[fm][0];
            float y1 = o[fm][fn][1] * linv[fm][0];
            float y2 = o[fm][fn][2] * linv[fm][1];
            float y3 = o[fm][fn][3] * linv[fm][1];
            __half h0 = __float2half(y0), h1 = __float2half(y1);
            __half h2 = __float2half(y2), h3 = __float2half(y3);
            size_t b0 = (size_t)r0 * KA2 + col;
            size_t b8 = b0 + 8 * KA2;
            *reinterpret_cast<uint32_t*>(A2o + b0) = pack_h2(h0, h1);
            *reinterpret_cast<uint32_t*>(A2o + b8) = pack_h2(h2, h3);
            *reinterpret_cast<uint32_t*>(A2o + b0 + KDIM) = pack_h2(
                __float2half(y0 - __half2float(h0)),
                __float2half(y1 - __half2float(h1)));
            *reinterpret_cast<uint32_t*>(A2o + b8 + KDIM) = pack_h2(
                __float2half(y2 - __half2float(h2)),
                __float2half(y3 - __half2float(h3)));
        }
    }
}

// ---------------------------------------------------------------------------
// Launch
// ---------------------------------------------------------------------------
extern "C" void kernel_launch(void* const* d_in, const int* in_sizes, int n_in,
                              void* d_out, int out_size)
{
    const float *q_embs, *k_embs, *v_embs, *w_q, *w_k, *w_v, *w_o;
    if (in_sizes[3] == D_MODEL * DIM_KV) {
        k_embs = (const float*)d_in[0];
        q_embs = (const float*)d_in[1];
        v_embs = (const float*)d_in[2];
        w_k    = (const float*)d_in[3];
        w_o    = (const float*)d_in[4];
        w_q    = (const float*)d_in[5];
        w_v    = (const float*)d_in[6];
    } else {
        q_embs = (const float*)d_in[0];
        k_embs = (const float*)d_in[1];
        v_embs = (const float*)d_in[2];
        w_q    = (const float*)d_in[3];
        w_k    = (const float*)d_in[4];
        w_v    = (const float*)d_in[5];
        w_o    = (const float*)d_in[6];
    }
    float* out = (float*)d_out;

    float *RC, *RS;
    __half *A2q, *A2k, *A2v, *A2o, *B2q, *B2k, *B2v, *B2o, *Q2, *K2h, *Vth;
    cudaGetSymbolAddress((void**)&A2q, g_A2q);
    cudaGetSymbolAddress((void**)&A2k, g_A2k);
    cudaGetSymbolAddress((void**)&A2v, g_A2v);
    cudaGetSymbolAddress((void**)&A2o, g_A2o);
    cudaGetSymbolAddress((void**)&B2q, g_B2q);
    cudaGetSymbolAddress((void**)&B2k, g_B2k);
    cudaGetSymbolAddress((void**)&B2v, g_B2v);
    cudaGetSymbolAddress((void**)&B2o, g_B2o);
    cudaGetSymbolAddress((void**)&Q2,  g_Q2);
    cudaGetSymbolAddress((void**)&K2h, g_K2h);
    cudaGetSymbolAddress((void**)&Vth, g_Vth);
    cudaGetSymbolAddress((void**)&RC,  g_rc);
    cudaGetSymbolAddress((void**)&RS,  g_rs);

    cudaFuncSetAttribute(gemm_uber_kernel,
                         cudaFuncAttributeMaxDynamicSharedMemorySize, GEMM_SMEM_BYTES);
    cudaFuncSetAttribute(gemm_o_kernel,
                         cudaFuncAttributeMaxDynamicSharedMemorySize, GEMM_SMEM_BYTES);
    cudaFuncSetAttribute(flash_hmma_kernel,
                         cudaFuncAttributeMaxDynamicSharedMemorySize, FLASH_SMEM_BYTES);

    rope_table_kernel<<<(T_SEQ * 32 + 255) / 256, 256>>>(RC, RS);                 // 1
    split_a3_kernel<<<dim3((T_SEQ * KDIM + 255) / 256, 1, 3), 256>>>(
        q_embs, k_embs, v_embs, A2q, A2k, A2v);                                   // 2
    split_b4_kernel<<<dim3(D_MODEL / 32, KDIM / 32, 4), dim3(32, 8)>>>(
        w_q, w_k, w_v, w_o, B2q, B2k, B2v, B2o);                                  // 3

    gemm_uber_kernel<<<384, 128, GEMM_SMEM_BYTES>>>(
        A2q, B2q, A2k, B2k, A2v, B2v, Q2, K2h, Vth, RC, RS);                      // 4 (profile slot)

    flash_hmma_kernel<<<dim3(T_SEQ / 256, NQH), 256, FLASH_SMEM_BYTES>>>(
        Q2, K2h, Vth, A2o);                                                       // 5

    gemm_o_kernel<<<dim3(D_MODEL / 128, T_SEQ / 128), 128, GEMM_SMEM_BYTES>>>(
        A2o, B2o, out);                                                           // 6
}

// round 14
// speedup vs baseline: 1.0716x; 1.0716x over previous
#include <cuda_runtime.h>
#include <cuda_bf16.h>
#include <cuda_fp16.h>
#include <math.h>
#include <stdint.h>

#define D_MODEL 2048
#define T_SEQ   2048
#define NQH     32
#define NKVH    8
#define HD      64
#define DIM_KV  512
#define KDIM    2048
#define KA2     (2*KDIM)       // fp16 2-term A width = 4096
#define PADH    72             // GEMM smem row stride (halves)
#define QPAD    136            // flash Q smem row stride (halves)
#define KVPAD   72             // flash K/V smem row stride (halves)

// ---------------------------------------------------------------------------
// Device-global scratch
// ---------------------------------------------------------------------------
__device__ __align__(16) __half g_A2q[T_SEQ * KA2];
__device__ __align__(16) __half g_A2k[T_SEQ * KA2];
__device__ __align__(16) __half g_A2v[T_SEQ * KA2];
__device__ __align__(16) __half g_A2o[T_SEQ * KA2];      // flash output [Oh|Ol]
__device__ __align__(16) __half g_B2q[D_MODEL * KDIM];
__device__ __align__(16) __half g_B2k[DIM_KV  * KDIM];
__device__ __align__(16) __half g_B2v[DIM_KV  * KDIM];
__device__ __align__(16) __half g_B2o[D_MODEL * KDIM];
__device__ __align__(16) __half g_Q2[NQH  * T_SEQ * 128]; // [h][t][Qh|Ql]
__device__ __align__(16) __half g_K2h[NKVH * T_SEQ * 64]; // [kvh][t][Kh]
__device__ __align__(16) __half g_Vth[DIM_KV * T_SEQ];    // V^T hi [d][t]
__device__ float g_rc[T_SEQ * 32];
__device__ float g_rs[T_SEQ * 32];

// ---------------------------------------------------------------------------
// PTX helpers
// ---------------------------------------------------------------------------
__device__ __forceinline__ uint32_t smem_u32(const void* p) {
    uint32_t a;
    asm("{ .reg .u64 t; cvta.to.shared.u64 t, %1; cvt.u32.u64 %0, t; }"
        : "=r"(a) : "l"(p));
    return a;
}

__device__ __forceinline__ void ldmatrix_x4(uint32_t& r0, uint32_t& r1,
                                            uint32_t& r2, uint32_t& r3,
                                            uint32_t addr) {
    asm volatile("ldmatrix.sync.aligned.m8n8.x4.shared.b16 {%0,%1,%2,%3}, [%4];"
                 : "=r"(r0), "=r"(r1), "=r"(r2), "=r"(r3) : "r"(addr));
}

__device__ __forceinline__ void mma16816(float* d, const uint32_t* a,
                                         uint32_t b0, uint32_t b1) {
    asm volatile(
        "mma.sync.aligned.m16n8k16.row.col.f32.f16.f16.f32 "
        "{%0,%1,%2,%3}, {%4,%5,%6,%7}, {%8,%9}, {%0,%1,%2,%3};"
        : "+f"(d[0]), "+f"(d[1]), "+f"(d[2]), "+f"(d[3])
        : "r"(a[0]), "r"(a[1]), "r"(a[2]), "r"(a[3]), "r"(b0), "r"(b1));
}

__device__ __forceinline__ void cp_async16(uint32_t saddr, const void* gaddr) {
    asm volatile("cp.async.cg.shared.global [%0], [%1], 16;"
                 :: "r"(saddr), "l"(gaddr));
}
#define CP_COMMIT() asm volatile("cp.async.commit_group;" ::: "memory")
#define CP_WAIT(n)  asm volatile("cp.async.wait_group %0;" :: "n"(n) : "memory")

__device__ __forceinline__ uint32_t pack_h2(__half a, __half b) {
    return ((uint32_t)__half_as_ushort(b) << 16) | __half_as_ushort(a);
}

// ---------------------------------------------------------------------------
// Conversions (merged launches)
// ---------------------------------------------------------------------------
__global__ void split_a3_kernel(const float* __restrict__ Xq,
                                const float* __restrict__ Xk,
                                const float* __restrict__ Xv,
                                __half* __restrict__ A2q,
                                __half* __restrict__ A2k,
                                __half* __restrict__ A2v)
{
    const float* X = (blockIdx.z == 0) ? Xq : (blockIdx.z == 1) ? Xk : Xv;
    __half* A2     = (blockIdx.z == 0) ? A2q : (blockIdx.z == 1) ? A2k : A2v;
    int idx = blockIdx.x * blockDim.x + threadIdx.x;
    if (idx >= T_SEQ * KDIM) return;
    int m = idx / KDIM, k = idx % KDIM;
    float x = X[idx];
    __half h = __float2half(x);
    __half l = __float2half(x - __half2float(h));
    size_t b = (size_t)m * KA2;
    A2[b + k]        = h;
    A2[b + KDIM + k] = l;
}

__global__ void split_b4_kernel(const float* __restrict__ Wq,
                                const float* __restrict__ Wk,
                                const float* __restrict__ Wv,
                                const float* __restrict__ Wo,
                                __half* __restrict__ B2q,
                                __half* __restrict__ B2k,
                                __half* __restrict__ B2v,
                                __half* __restrict__ B2o)
{
    const int z = blockIdx.z;
    const float* W = (z == 0) ? Wq : (z == 1) ? Wk : (z == 2) ? Wv : Wo;
    __half* B2     = (z == 0) ? B2q : (z == 1) ? B2k : (z == 2) ? B2v : B2o;
    const int N    = (z == 1 || z == 2) ? DIM_KV : D_MODEL;

    __shared__ float tile[32][33];
    int n0 = blockIdx.x * 32, k0 = blockIdx.y * 32;
    if (n0 >= N) return;
    int tx = threadIdx.x, ty = threadIdx.y;
    #pragma unroll
    for (int i = 0; i < 32; i += 8)
        tile[ty + i][tx] = W[(size_t)(k0 + ty + i) * N + n0 + tx];
    __syncthreads();
    #pragma unroll
    for (int i = 0; i < 32; i += 8) {
        int n = n0 + ty + i;
        B2[(size_t)n * KDIM + k0 + tx] = __float2half(tile[tx][ty + i]);
    }
}

__global__ void rope_table_kernel(float* __restrict__ rc, float* __restrict__ rs)
{
    int idx = blockIdx.x * blockDim.x + threadIdx.x;
    if (idx >= T_SEQ * 32) return;
    int t = idx >> 5, i = idx & 31;
    float invf = (float)pow(500000.0, -(double)i / 32.0);
    float angf = (float)t * invf;
    double ang = (double)angf;
    rc[idx] = (float)cos(ang);
    rs[idx] = (float)sin(ang);
}

// ---------------------------------------------------------------------------
// Shared GEMM mainloop (CTA 128x128, 128 threads, 4 warps 64x64, DB cp.async)
// ---------------------------------------------------------------------------
#define GEMM_SMEM_BYTES (4 * 128 * PADH * 2)   // 73728

__device__ __forceinline__ void ldgsts_tileS(uint32_t sBase, const __half* G,
                                             int k0, int tid, int strideH)
{
    #pragma unroll
    for (int i = 0; i < 8; i++) {
        int id  = tid + (i << 7);
        int row = id >> 3;
        int c8  = id & 7;
        cp_async16(sBase + (uint32_t)(row * PADH + c8 * 8) * 2,
                   G + (size_t)row * strideH + k0 + c8 * 8);
    }
}

__device__ __forceinline__ void gemm_mainloop(
    uint32_t shBase, const __half* Ag, const __half* Bg,
    int tid, int lane, int wm, int wn, float acc[4][8][4])
{
    const uint32_t TILE_B = 128 * PADH * 2;
    const int nCh = KA2 / 64;   // 64

    ldgsts_tileS(shBase + 0 * TILE_B, Ag, 0, tid, KA2);
    ldgsts_tileS(shBase + 2 * TILE_B, Bg, 0, tid, KDIM);
    CP_COMMIT();

    const int lrow = (lane & 7) + ((lane >> 3) & 1) * 8;
    const int lcol = (lane >> 4) * 8;

    for (int c = 0; c < nCh; c++) {
        const int s = c & 1;
        if (c + 1 < nCh) {
            const int s2 = s ^ 1;
            ldgsts_tileS(shBase + s2 * TILE_B,       Ag, (c + 1) * 64, tid, KA2);
            ldgsts_tileS(shBase + (2 + s2) * TILE_B, Bg, (((c + 1) & 31)) * 64, tid, KDIM);
            CP_COMMIT();
            CP_WAIT(1);
        } else {
            CP_WAIT(0);
        }
        __syncthreads();

        const uint32_t aB = shBase + s * TILE_B;
        const uint32_t bB = shBase + (2 + s) * TILE_B;
        #pragma unroll
        for (int ks = 0; ks < 4; ks++) {
            const int k16 = ks * 16;
            uint32_t af[4][4], bfr[4][4];
            #pragma unroll
            for (int fm = 0; fm < 4; fm++)
                ldmatrix_x4(af[fm][0], af[fm][1], af[fm][2], af[fm][3],
                    aB + (uint32_t)((wm * 64 + fm * 16 + lrow) * PADH + k16 + lcol) * 2);
            #pragma unroll
            for (int fp = 0; fp < 4; fp++)
                ldmatrix_x4(bfr[fp][0], bfr[fp][1], bfr[fp][2], bfr[fp][3],
                    bB + (uint32_t)((wn * 64 + fp * 16 + lrow) * PADH + k16 + lcol) * 2);
            #pragma unroll
            for (int fm = 0; fm < 4; fm++)
                #pragma unroll
                for (int fn = 0; fn < 8; fn++) {
                    uint32_t b0 = (fn & 1) ? bfr[fn >> 1][1] : bfr[fn >> 1][0];
                    uint32_t b1 = (fn & 1) ? bfr[fn >> 1][3] : bfr[fn >> 1][2];
                    mma16816(acc[fm][fn], af[fm], b0, b1);
                }
        }
        __syncthreads();
    }
}

// ---------------------------------------------------------------------------
// Uber projection kernel: one launch computes Q (256 CTAs), K (64), V (64).
// ---------------------------------------------------------------------------
__global__ __launch_bounds__(128, 2) void gemm_uber_kernel(
    const __half* __restrict__ A2q, const __half* __restrict__ B2q,
    const __half* __restrict__ A2k, const __half* __restrict__ B2k,
    const __half* __restrict__ A2v, const __half* __restrict__ B2v,
    __half* __restrict__ Q2, __half* __restrict__ K2h, __half* __restrict__ Vth,
    const float* __restrict__ rc, const float* __restrict__ rs)
{
    extern __shared__ __half sh[];
    uint32_t shBase = smem_u32(sh);
    const int tid  = threadIdx.x;
    const int lane = tid & 31;
    const int wid  = tid >> 5;
    const int wm   = wid & 1;
    const int wn   = wid >> 1;

    const int bid = blockIdx.x;
    int mode, rowBase, colBase;
    const __half *Ap, *Bp;
    if (bid < 256) {          // Q: 16x16 tiles
        mode = 0;
        rowBase = (bid >> 4) * 128;
        colBase = (bid & 15) * 128;
        Ap = A2q; Bp = B2q;
    } else if (bid < 320) {   // K: 16x4 tiles
        mode = 1;
        int b = bid - 256;
        rowBase = (b >> 2) * 128;
        colBase = (b & 3) * 128;
        Ap = A2k; Bp = B2k;
    } else {                  // V
        mode = 2;
        int b = bid - 320;
        rowBase = (b >> 2) * 128;
        colBase = (b & 3) * 128;
        Ap = A2v; Bp = B2v;
    }

    float acc[4][8][4];
    #pragma unroll
    for (int i = 0; i < 4; i++)
        #pragma unroll
        for (int j = 0; j < 8; j++)
            #pragma unroll
            for (int q = 0; q < 4; q++) acc[i][j][q] = 0.0f;

    gemm_mainloop(shBase, Ap + (size_t)rowBase * KA2, Bp + (size_t)colBase * KDIM,
                  tid, lane, wm, wn, acc);

    #pragma unroll
    for (int fm = 0; fm < 4; fm++) {
        #pragma unroll
        for (int fn = 0; fn < 8; fn++) {
            int r0 = rowBase + wm * 64 + fm * 16 + (lane >> 2);
            int c0 = colBase + wn * 64 + fn * 8 + (lane & 3) * 2;
            float a0 = acc[fm][fn][0], a1 = acc[fm][fn][1];
            float a2 = acc[fm][fn][2], a3 = acc[fm][fn][3];
            if (mode == 2) {
                Vth[(size_t)c0 * T_SEQ + r0]           = __float2half(a0);
                Vth[(size_t)(c0 + 1) * T_SEQ + r0]     = __float2half(a1);
                Vth[(size_t)c0 * T_SEQ + r0 + 8]       = __float2half(a2);
                Vth[(size_t)(c0 + 1) * T_SEQ + r0 + 8] = __float2half(a3);
            } else {
                const int h = c0 >> 6;
                const int d = c0 & 63;
                const int i = d >> 1;
                float c1 = rc[r0 * 32 + i],       s1 = rs[r0 * 32 + i];
                float c2 = rc[(r0 + 8) * 32 + i], s2 = rs[(r0 + 8) * 32 + i];
                float y0 = a0 * c1 - a1 * s1, y1 = a0 * s1 + a1 * c1;
                float y2 = a2 * c2 - a3 * s2, y3 = a2 * s2 + a3 * c2;
                __half h0 = __float2half(y0), h1 = __float2half(y1);
                __half h2 = __float2half(y2), h3 = __float2half(y3);
                if (mode == 0) {
                    size_t b0 = ((size_t)h * T_SEQ + r0) * 128 + d;
                    size_t b8 = b0 + 8 * 128;
                    *reinterpret_cast<uint32_t*>(Q2 + b0) = pack_h2(h0, h1);
                    *reinterpret_cast<uint32_t*>(Q2 + b8) = pack_h2(h2, h3);
                    *reinterpret_cast<uint32_t*>(Q2 + b0 + 64) = pack_h2(
                        __float2half(y0 - __half2float(h0)),
                        __float2half(y1 - __half2float(h1)));
                    *reinterpret_cast<uint32_t*>(Q2 + b8 + 64) = pack_h2(
                        __float2half(y2 - __half2float(h2)),
                        __float2half(y3 - __half2float(h3)));
                } else {
                    size_t b0 = ((size_t)h * T_SEQ + r0) * 64 + d;
                    size_t b8 = b0 + 8 * 64;
                    *reinterpret_cast<uint32_t*>(K2h + b0) = pack_h2(h0, h1);
                    *reinterpret_cast<uint32_t*>(K2h + b8) = pack_h2(h2, h3);
                }
            }
        }
    }
}

// O-projection GEMM (fp32 store)
__global__ __launch_bounds__(128, 2) void gemm_o_kernel(
    const __half* __restrict__ A2, const __half* __restrict__ B2,
    float* __restrict__ C)
{
    extern __shared__ __half sh[];
    uint32_t shBase = smem_u32(sh);
    const int tid  = threadIdx.x;
    const int lane = tid & 31;
    const int wid  = tid >> 5;
    const int wm   = wid & 1;
    const int wn   = wid >> 1;
    const int rowBase = blockIdx.y * 128;
    const int colBase = blockIdx.x * 128;

    float acc[4][8][4];
    #pragma unroll
    for (int i = 0; i < 4; i++)
        #pragma unroll
        for (int j = 0; j < 8; j++)
            #pragma unroll
            for (int q = 0; q < 4; q++) acc[i][j][q] = 0.0f;

    gemm_mainloop(shBase, A2 + (size_t)rowBase * KA2, B2 + (size_t)colBase * KDIM,
                  tid, lane, wm, wn, acc);

    #pragma unroll
    for (int fm = 0; fm < 4; fm++) {
        #pragma unroll
        for (int fn = 0; fn < 8; fn++) {
            int r0 = rowBase + wm * 64 + fm * 16 + (lane >> 2);
            int c0 = colBase + wn * 64 + fn * 8 + (lane & 3) * 2;
            *reinterpret_cast<float2*>(&C[(size_t)r0 * D_MODEL + c0]) =
                make_float2(acc[fm][fn][0], acc[fm][fn][1]);
            *reinterpret_cast<float2*>(&C[(size_t)(r0 + 8) * D_MODEL + c0]) =
                make_float2(acc[fm][fn][2], acc[fm][fn][3]);
        }
    }
}

// ---------------------------------------------------------------------------
// HMMA flash attention (R12's proven 128-thread version):
// CTA = 128 q-rows x 1 head, 4 warps, reversed schedule.
// ---------------------------------------------------------------------------
#define FLASH_SMEM_BYTES ((128 * QPAD + 64 * KVPAD + 64 * KVPAD) * 2)

__global__ __launch_bounds__(128) void flash_hmma_kernel(
    const __half* __restrict__ Q2,
    const __half* __restrict__ K2h,
    const __half* __restrict__ Vth,
    __half* __restrict__ A2o)
{
    extern __shared__ __half fs[];
    const uint32_t QsA = smem_u32(fs);
    const uint32_t KsA = QsA + 128 * QPAD * 2;
    const uint32_t VsA = KsA + 64 * KVPAD * 2;

    const int tid = threadIdx.x, lane = tid & 31, wq = tid >> 5;
    const int h = blockIdx.y, kvh = h >> 2;
    const int m0 = (gridDim.x - 1 - (int)blockIdx.x) * 128;

    const int g  = lane >> 2;
    const int tg = lane & 3;
    const int lrow = (lane & 7) + ((lane >> 3) & 1) * 8;
    const int lcol = (lane >> 4) * 8;
    const float NEG = -1e30f;
    const float scale = 0.125f;

    {
        const __half* Qg = Q2 + ((size_t)h * T_SEQ + m0) * 128;
        #pragma unroll
        for (int u = 0; u < 16; u++) {
            int id = tid + u * 128;
            int row = id >> 4, c = id & 15;
            cp_async16(QsA + (uint32_t)(row * QPAD + c * 8) * 2,
                       Qg + (size_t)row * 128 + c * 8);
        }
        CP_COMMIT();
    }

    float o[2][8][4];
    #pragma unroll
    for (int i = 0; i < 2; i++)
        #pragma unroll
        for (int j = 0; j < 8; j++)
            #pragma unroll
            for (int q = 0; q < 4; q++) o[i][j][q] = 0.0f;
    float mrow[2][2] = {{NEG, NEG}, {NEG, NEG}};
    float lacc[2][2] = {{0.f, 0.f}, {0.f, 0.f}};

    const int nT = m0 / 64 + 2;
    for (int jt = 0; jt < nT; jt++) {
        const int j0 = jt * 64;
        __syncthreads();
        #pragma unroll
        for (int u = 0; u < 4; u++) {
            int id = tid + u * 128;
            int row = id >> 3, c = id & 7;
            cp_async16(KsA + (uint32_t)(row * KVPAD + c * 8) * 2,
                       K2h + ((size_t)kvh * T_SEQ + j0 + row) * 64 + c * 8);
        }
        #pragma unroll
        for (int u = 0; u < 4; u++) {
            int id = tid + u * 128;
            int row = id >> 3, c = id & 7;
            cp_async16(VsA + (uint32_t)(row * KVPAD + c * 8) * 2,
                       Vth + (size_t)(kvh * 64 + row) * T_SEQ + j0 + c * 8);
        }
        CP_COMMIT();
        CP_WAIT(0);
        __syncthreads();

        float s[2][8][4];
        #pragma unroll
        for (int i = 0; i < 2; i++)
            #pragma unroll
            for (int j = 0; j < 8; j++)
                #pragma unroll
                for (int q = 0; q < 4; q++) s[i][j][q] = 0.0f;

        #pragma unroll
        for (int kc = 0; kc < 8; kc++) {
            uint32_t af[2][4], bk[4][4];
            #pragma unroll
            for (int fm = 0; fm < 2; fm++)
                ldmatrix_x4(af[fm][0], af[fm][1], af[fm][2], af[fm][3],
                    QsA + (uint32_t)((wq * 32 + fm * 16 + lrow) * QPAD + kc * 16 + lcol) * 2);
            #pragma unroll
            for (int fp = 0; fp < 4; fp++)
                ldmatrix_x4(bk[fp][0], bk[fp][1], bk[fp][2], bk[fp][3],
                    KsA + (uint32_t)((fp * 16 + lrow) * KVPAD + (kc & 3) * 16 + lcol) * 2);
            #pragma unroll
            for (int fm = 0; fm < 2; fm++)
                #pragma unroll
                for (int fn = 0; fn < 8; fn++) {
                    uint32_t b0 = (fn & 1) ? bk[fn >> 1][1] : bk[fn >> 1][0];
                    uint32_t b1 = (fn & 1) ? bk[fn >> 1][3] : bk[fn >> 1][2];
                    mma16816(s[fm][fn], af[fm], b0, b1);
                }
        }

        #pragma unroll
        for (int fm = 0; fm < 2; fm++) {
            const int r0 = m0 + wq * 32 + fm * 16 + g;
            const int r1 = r0 + 8;
            float mx0 = NEG, mx1 = NEG;
            #pragma unroll
            for (int fn = 0; fn < 8; fn++) {
                const int cb = j0 + fn * 8 + tg * 2;
                float v0 = (cb     <= r0) ? s[fm][fn][0] * scale : NEG;
                float v1 = (cb + 1 <= r0) ? s[fm][fn][1] * scale : NEG;
                float v2 = (cb     <= r1) ? s[fm][fn][2] * scale : NEG;
                float v3 = (cb + 1 <= r1) ? s[fm][fn][3] * scale : NEG;
                s[fm][fn][0] = v0; s[fm][fn][1] = v1;
                s[fm][fn][2] = v2; s[fm][fn][3] = v3;
                mx0 = fmaxf(mx0, fmaxf(v0, v1));
                mx1 = fmaxf(mx1, fmaxf(v2, v3));
            }
            mx0 = fmaxf(mx0, __shfl_xor_sync(0xffffffffu, mx0, 1));
            mx0 = fmaxf(mx0, __shfl_xor_sync(0xffffffffu, mx0, 2));
            mx1 = fmaxf(mx1, __shfl_xor_sync(0xffffffffu, mx1, 1));
            mx1 = fmaxf(mx1, __shfl_xor_sync(0xffffffffu, mx1, 2));
            const float mn0 = fmaxf(mrow[fm][0], mx0);
            const float mn1 = fmaxf(mrow[fm][1], mx1);
            const float c0 = __expf(mrow[fm][0] - mn0);
            const float c1 = __expf(mrow[fm][1] - mn1);
            mrow[fm][0] = mn0; mrow[fm][1] = mn1;
            float ls0 = 0.f, ls1 = 0.f;
            #pragma unroll
            for (int fn = 0; fn < 8; fn++) {
                float p0 = __expf(s[fm][fn][0] - mn0);
                float p1 = __expf(s[fm][fn][1] - mn0);
                float p2 = __expf(s[fm][fn][2] - mn1);
                float p3 = __expf(s[fm][fn][3] - mn1);
                s[fm][fn][0] = p0; s[fm][fn][1] = p1;
                s[fm][fn][2] = p2; s[fm][fn][3] = p3;
                ls0 += p0 + p1; ls1 += p2 + p3;
                o[fm][fn][0] *= c0; o[fm][fn][1] *= c0;
                o[fm][fn][2] *= c1; o[fm][fn][3] *= c1;
            }
            lacc[fm][0] = lacc[fm][0] * c0 + ls0;
            lacc[fm][1] = lacc[fm][1] * c1 + ls1;
        }

        #pragma unroll
        for (int kc2 = 0; kc2 < 4; kc2++) {
            uint32_t aPh[2][4], aPl[2][4];
            #pragma unroll
            for (int fm = 0; fm < 2; fm++) {
                #pragma unroll
                for (int half = 0; half < 2; half++) {
                    const int fr = 2 * kc2 + half;
                    float p0 = s[fm][fr][0], p1 = s[fm][fr][1];
                    float p2 = s[fm][fr][2], p3 = s[fm][fr][3];
                    __half h0 = __float2half(p0), h1 = __float2half(p1);
                    __half h2 = __float2half(p2), h3 = __float2half(p3);
                    aPh[fm][half * 2 + 0] = pack_h2(h0, h1);
                    aPh[fm][half * 2 + 1] = pack_h2(h2, h3);
                    aPl[fm][half * 2 + 0] = pack_h2(
                        __float2half(p0 - __half2float(h0)),
                        __float2half(p1 - __half2float(h1)));
                    aPl[fm][half * 2 + 1] = pack_h2(
                        __float2half(p2 - __half2float(h2)),
                        __float2half(p3 - __half2float(h3)));
                }
            }
            uint32_t bv[4][4];
            #pragma unroll
            for (int fp = 0; fp < 4; fp++)
                ldmatrix_x4(bv[fp][0], bv[fp][1], bv[fp][2], bv[fp][3],
                    VsA + (uint32_t)((fp * 16 + lrow) * KVPAD + kc2 * 16 + lcol) * 2);
            #pragma unroll
            for (int fm = 0; fm < 2; fm++)
                #pragma unroll
                for (int fn = 0; fn < 8; fn++) {
                    uint32_t b0 = (fn & 1) ? bv[fn >> 1][1] : bv[fn >> 1][0];
                    uint32_t b1 = (fn & 1) ? bv[fn >> 1][3] : bv[fn >> 1][2];
                    mma16816(o[fm][fn], aPh[fm], b0, b1);
                    mma16816(o[fm][fn], aPl[fm], b0, b1);
                }
        }
    }

    float linv[2][2];
    #pragma unroll
    for (int fm = 0; fm < 2; fm++)
        #pragma unroll
        for (int half = 0; half < 2; half++) {
            float lv = lacc[fm][half];
            lv += __shfl_xor_sync(0xffffffffu, lv, 1);
            lv += __shfl_xor_sync(0xffffffffu, lv, 2);
            linv[fm][half] = 1.0f / lv;
        }
    #pragma unroll
    for (int fm = 0; fm < 2; fm++) {
        const int r0 = m0 + wq * 32 + fm * 16 + g;
        #pragma unroll
        for (int fn = 0; fn < 8; fn++) {
            const int col = h * HD + fn * 8 + tg * 2;
            float y0 = o[fm][fn][0] * linv[fm][0];
            float y1 = o[fm][fn][1] * linv[fm][0];
            float y2 = o[fm][fn][2] * linv[fm][1];
            float y3 = o[fm][fn][3] * linv[fm][1];
            __half h0 = __float2half(y0), h1 = __float2half(y1);
            __half h2 = __float2half(y2), h3 = __float2half(y3);
            size_t b0 = (size_t)r0 * KA2 + col;
            size_t b8 = b0 + 8 * KA2;
            *reinterpret_cast<uint32_t*>(A2o + b0) = pack_h2(h0, h1);
            *reinterpret_cast<uint32_t*>(A2o + b8) = pack_h2(h2, h3);
            *reinterpret_cast<uint32_t*>(A2o + b0 + KDIM) = pack_h2(
                __float2half(y0 - __half2float(h0)),
                __float2half(y1 - __half2float(h1)));
            *reinterpret_cast<uint32_t*>(A2o + b8 + KDIM) = pack_h2(
                __float2half(y2 - __half2float(h2)),
                __float2half(y3 - __half2float(h3)));
        }
    }
}

// ---------------------------------------------------------------------------
// Launch
// ---------------------------------------------------------------------------
extern "C" void kernel_launch(void* const* d_in, const int* in_sizes, int n_in,
                              void* d_out, int out_size)
{
    const float *q_embs, *k_embs, *v_embs, *w_q, *w_k, *w_v, *w_o;
    if (in_sizes[3] == D_MODEL * DIM_KV) {
        k_embs = (const float*)d_in[0];
        q_embs = (const float*)d_in[1];
        v_embs = (const float*)d_in[2];
        w_k    = (const float*)d_in[3];
        w_o    = (const float*)d_in[4];
        w_q    = (const float*)d_in[5];
        w_v    = (const float*)d_in[6];
    } else {
        q_embs = (const float*)d_in[0];
        k_embs = (const float*)d_in[1];
        v_embs = (const float*)d_in[2];
        w_q    = (const float*)d_in[3];
        w_k    = (const float*)d_in[4];
        w_v    = (const float*)d_in[5];
        w_o    = (const float*)d_in[6];
    }
    float* out = (float*)d_out;

    float *RC, *RS;
    __half *A2q, *A2k, *A2v, *A2o, *B2q, *B2k, *B2v, *B2o, *Q2, *K2h, *Vth;
    cudaGetSymbolAddress((void**)&A2q, g_A2q);
    cudaGetSymbolAddress((void**)&A2k, g_A2k);
    cudaGetSymbolAddress((void**)&A2v, g_A2v);
    cudaGetSymbolAddress((void**)&A2o, g_A2o);
    cudaGetSymbolAddress((void**)&B2q, g_B2q);
    cudaGetSymbolAddress((void**)&B2k, g_B2k);
    cudaGetSymbolAddress((void**)&B2v, g_B2v);
    cudaGetSymbolAddress((void**)&B2o, g_B2o);
    cudaGetSymbolAddress((void**)&Q2,  g_Q2);
    cudaGetSymbolAddress((void**)&K2h, g_K2h);
    cudaGetSymbolAddress((void**)&Vth, g_Vth);
    cudaGetSymbolAddress((void**)&RC,  g_rc);
    cudaGetSymbolAddress((void**)&RS,  g_rs);

    cudaFuncSetAttribute(gemm_uber_kernel,
                         cudaFuncAttributeMaxDynamicSharedMemorySize, GEMM_SMEM_BYTES);
    cudaFuncSetAttribute(gemm_o_kernel,
                         cudaFuncAttributeMaxDynamicSharedMemorySize, GEMM_SMEM_BYTES);
    cudaFuncSetAttribute(flash_hmma_kernel,
                         cudaFuncAttributeMaxDynamicSharedMemorySize, FLASH_SMEM_BYTES);

    rope_table_kernel<<<(T_SEQ * 32 + 255) / 256, 256>>>(RC, RS);                 // 1
    split_a3_kernel<<<dim3((T_SEQ * KDIM + 255) / 256, 1, 3), 256>>>(
        q_embs, k_embs, v_embs, A2q, A2k, A2v);                                   // 2
    split_b4_kernel<<<dim3(D_MODEL / 32, KDIM / 32, 4), dim3(32, 8)>>>(
        w_q, w_k, w_v, w_o, B2q, B2k, B2v, B2o);                                  // 3

    gemm_uber_kernel<<<384, 128, GEMM_SMEM_BYTES>>>(
        A2q, B2q, A2k, B2k, A2v, B2v, Q2, K2h, Vth, RC, RS);                      // 4 (profile slot)

    flash_hmma_kernel<<<dim3(T_SEQ / 128, NQH), 128, FLASH_SMEM_BYTES>>>(
        Q2, K2h, Vth, A2o);                                                       // 5

    gemm_o_kernel<<<dim3(D_MODEL / 128, T_SEQ / 128), 128, GEMM_SMEM_BYTES>>>(
        A2o, B2o, out);                                                           // 6
}

// round 15
// speedup vs baseline: 1.3454x; 1.2556x over previous
#include <cuda_runtime.h>
#include <cuda_bf16.h>
#include <cuda_fp16.h>
#include <math.h>
#include <stdint.h>

#define D_MODEL 2048
#define T_SEQ   2048
#define NQH     32
#define NKVH    8
#define HD      64
#define DIM_KV  512
#define KDIM    2048
#define KA2     (2*KDIM)       // fp16 2-term A width = 4096
#define PADH    72             // GEMM smem row stride (halves)
#define QPAD    136            // flash Q smem row stride (halves)
#define KVPAD   72             // flash K/V smem row stride (halves)

// ---------------------------------------------------------------------------
// Device-global scratch
// ---------------------------------------------------------------------------
__device__ __align__(16) __half g_A2q[T_SEQ * KA2];
__device__ __align__(16) __half g_A2k[T_SEQ * KA2];
__device__ __align__(16) __half g_A2v[T_SEQ * KA2];
__device__ __align__(16) __half g_Aoh[T_SEQ * KDIM];     // flash output, hi only
__device__ __align__(16) __half g_B2q[D_MODEL * KDIM];
__device__ __align__(16) __half g_B2k[DIM_KV  * KDIM];
__device__ __align__(16) __half g_B2v[DIM_KV  * KDIM];
__device__ __align__(16) __half g_B2o[D_MODEL * KDIM];
__device__ __align__(16) __half g_Q2[NQH  * T_SEQ * 128]; // [h][t][Qh|Ql]
__device__ __align__(16) __half g_K2h[NKVH * T_SEQ * 64]; // [kvh][t][Kh]
__device__ __align__(16) __half g_Vth[DIM_KV * T_SEQ];    // V^T hi [d][t]
__device__ float g_rc[T_SEQ * 32];
__device__ float g_rs[T_SEQ * 32];

// ---------------------------------------------------------------------------
// PTX helpers
// ---------------------------------------------------------------------------
__device__ __forceinline__ uint32_t smem_u32(const void* p) {
    uint32_t a;
    asm("{ .reg .u64 t; cvta.to.shared.u64 t, %1; cvt.u32.u64 %0, t; }"
        : "=r"(a) : "l"(p));
    return a;
}

__device__ __forceinline__ void ldmatrix_x4(uint32_t& r0, uint32_t& r1,
                                            uint32_t& r2, uint32_t& r3,
                                            uint32_t addr) {
    asm volatile("ldmatrix.sync.aligned.m8n8.x4.shared.b16 {%0,%1,%2,%3}, [%4];"
                 : "=r"(r0), "=r"(r1), "=r"(r2), "=r"(r3) : "r"(addr));
}

__device__ __forceinline__ void mma16816(float* d, const uint32_t* a,
                                         uint32_t b0, uint32_t b1) {
    asm volatile(
        "mma.sync.aligned.m16n8k16.row.col.f32.f16.f16.f32 "
        "{%0,%1,%2,%3}, {%4,%5,%6,%7}, {%8,%9}, {%0,%1,%2,%3};"
        : "+f"(d[0]), "+f"(d[1]), "+f"(d[2]), "+f"(d[3])
        : "r"(a[0]), "r"(a[1]), "r"(a[2]), "r"(a[3]), "r"(b0), "r"(b1));
}

__device__ __forceinline__ void cp_async16(uint32_t saddr, const void* gaddr) {
    asm volatile("cp.async.cg.shared.global [%0], [%1], 16;"
                 :: "r"(saddr), "l"(gaddr));
}
#define CP_COMMIT() asm volatile("cp.async.commit_group;" ::: "memory")
#define CP_WAIT(n)  asm volatile("cp.async.wait_group %0;" :: "n"(n) : "memory")

__device__ __forceinline__ uint32_t pack_h2(__half a, __half b) {
    return ((uint32_t)__half_as_ushort(b) << 16) | __half_as_ushort(a);
}

// ---------------------------------------------------------------------------
// Conversions (merged + vectorized)
// ---------------------------------------------------------------------------
__global__ void split_a3_kernel(const float* __restrict__ Xq,
                                const float* __restrict__ Xk,
                                const float* __restrict__ Xv,
                                __half* __restrict__ A2q,
                                __half* __restrict__ A2k,
                                __half* __restrict__ A2v)
{
    const float* X = (blockIdx.z == 0) ? Xq : (blockIdx.z == 1) ? Xk : Xv;
    __half* A2     = (blockIdx.z == 0) ? A2q : (blockIdx.z == 1) ? A2k : A2v;
    int idx = blockIdx.x * blockDim.x + threadIdx.x;      // one float4 each
    if (idx >= T_SEQ * (KDIM / 4)) return;
    int m  = idx / (KDIM / 4);
    int k4 = (idx % (KDIM / 4)) * 4;
    float4 x = *reinterpret_cast<const float4*>(X + (size_t)m * KDIM + k4);
    __half h0 = __float2half(x.x), h1 = __float2half(x.y);
    __half h2 = __float2half(x.z), h3 = __float2half(x.w);
    uint2 hi = make_uint2(pack_h2(h0, h1), pack_h2(h2, h3));
    uint2 lo = make_uint2(
        pack_h2(__float2half(x.x - __half2float(h0)),
                __float2half(x.y - __half2float(h1))),
        pack_h2(__float2half(x.z - __half2float(h2)),
                __float2half(x.w - __half2float(h3))));
    size_t b = (size_t)m * KA2 + k4;
    *reinterpret_cast<uint2*>(A2 + b)        = hi;
    *reinterpret_cast<uint2*>(A2 + b + KDIM) = lo;
}

__global__ void split_b4_kernel(const float* __restrict__ Wq,
                                const float* __restrict__ Wk,
                                const float* __restrict__ Wv,
                                const float* __restrict__ Wo,
                                __half* __restrict__ B2q,
                                __half* __restrict__ B2k,
                                __half* __restrict__ B2v,
                                __half* __restrict__ B2o)
{
    const int z = blockIdx.z;
    const float* W = (z == 0) ? Wq : (z == 1) ? Wk : (z == 2) ? Wv : Wo;
    __half* B2     = (z == 0) ? B2q : (z == 1) ? B2k : (z == 2) ? B2v : B2o;
    const int N    = (z == 1 || z == 2) ? DIM_KV : D_MODEL;

    __shared__ float tile[32][33];
    int n0 = blockIdx.x * 32, k0 = blockIdx.y * 32;
    if (n0 >= N) return;
    int tx = threadIdx.x, ty = threadIdx.y;   // 32 x 8
    #pragma unroll
    for (int i = 0; i < 32; i += 8)
        tile[ty + i][tx] = W[(size_t)(k0 + ty + i) * N + n0 + tx];
    __syncthreads();
    // vectorized store: 256 threads, each writes 4 k-values (uint2)
    int tid = ty * 32 + tx;
    int nl  = tid >> 3;            // 0..31
    int k4  = (tid & 7) * 4;       // 0..28
    __half h0 = __float2half(tile[k4 + 0][nl]);
    __half h1 = __float2half(tile[k4 + 1][nl]);
    __half h2 = __float2half(tile[k4 + 2][nl]);
    __half h3 = __float2half(tile[k4 + 3][nl]);
    *reinterpret_cast<uint2*>(B2 + (size_t)(n0 + nl) * KDIM + k0 + k4) =
        make_uint2(pack_h2(h0, h1), pack_h2(h2, h3));
}

__global__ void rope_table_kernel(float* __restrict__ rc, float* __restrict__ rs)
{
    int idx = blockIdx.x * blockDim.x + threadIdx.x;
    if (idx >= T_SEQ * 32) return;
    int t = idx >> 5, i = idx & 31;
    float invf = (float)pow(500000.0, -(double)i / 32.0);
    float angf = (float)t * invf;
    double ang = (double)angf;
    rc[idx] = (float)cos(ang);
    rs[idx] = (float)sin(ang);
}

// ---------------------------------------------------------------------------
// Shared GEMM mainloop. A stride / chunk count / B wrap parameterized.
// ---------------------------------------------------------------------------
#define GEMM_SMEM_BYTES (4 * 128 * PADH * 2)   // 73728

__device__ __forceinline__ void ldgsts_tileS(uint32_t sBase, const __half* G,
                                             int k0, int tid, int strideH)
{
    #pragma unroll
    for (int i = 0; i < 8; i++) {
        int id  = tid + (i << 7);
        int row = id >> 3;
        int c8  = id & 7;
        cp_async16(sBase + (uint32_t)(row * PADH + c8 * 8) * 2,
                   G + (size_t)row * strideH + k0 + c8 * 8);
    }
}

__device__ __forceinline__ void gemm_mainloop(
    uint32_t shBase, const __half* Ag, const __half* Bg,
    int tid, int lane, int wm, int wn, float acc[4][8][4],
    int nCh, int strideA, int bMask)
{
    const uint32_t TILE_B = 128 * PADH * 2;

    ldgsts_tileS(shBase + 0 * TILE_B, Ag, 0, tid, strideA);
    ldgsts_tileS(shBase + 2 * TILE_B, Bg, 0, tid, KDIM);
    CP_COMMIT();

    const int lrow = (lane & 7) + ((lane >> 3) & 1) * 8;
    const int lcol = (lane >> 4) * 8;

    for (int c = 0; c < nCh; c++) {
        const int s = c & 1;
        if (c + 1 < nCh) {
            const int s2 = s ^ 1;
            ldgsts_tileS(shBase + s2 * TILE_B,       Ag, (c + 1) * 64, tid, strideA);
            ldgsts_tileS(shBase + (2 + s2) * TILE_B, Bg, ((c + 1) & bMask) * 64, tid, KDIM);
            CP_COMMIT();
            CP_WAIT(1);
        } else {
            CP_WAIT(0);
        }
        __syncthreads();

        const uint32_t aB = shBase + s * TILE_B;
        const uint32_t bB = shBase + (2 + s) * TILE_B;
        #pragma unroll
        for (int ks = 0; ks < 4; ks++) {
            const int k16 = ks * 16;
            uint32_t af[4][4], bfr[4][4];
            #pragma unroll
            for (int fm = 0; fm < 4; fm++)
                ldmatrix_x4(af[fm][0], af[fm][1], af[fm][2], af[fm][3],
                    aB + (uint32_t)((wm * 64 + fm * 16 + lrow) * PADH + k16 + lcol) * 2);
            #pragma unroll
            for (int fp = 0; fp < 4; fp++)
                ldmatrix_x4(bfr[fp][0], bfr[fp][1], bfr[fp][2], bfr[fp][3],
                    bB + (uint32_t)((wn * 64 + fp * 16 + lrow) * PADH + k16 + lcol) * 2);
            #pragma unroll
            for (int fm = 0; fm < 4; fm++)
                #pragma unroll
                for (int fn = 0; fn < 8; fn++) {
                    uint32_t b0 = (fn & 1) ? bfr[fn >> 1][1] : bfr[fn >> 1][0];
                    uint32_t b1 = (fn & 1) ? bfr[fn >> 1][3] : bfr[fn >> 1][2];
                    mma16816(acc[fm][fn], af[fm], b0, b1);
                }
        }
        __syncthreads();
    }
}

// ---------------------------------------------------------------------------
// Uber projection kernel: Q (256 CTAs) + K (64) + V (64) in one launch.
// ---------------------------------------------------------------------------
__global__ __launch_bounds__(128, 2) void gemm_uber_kernel(
    const __half* __restrict__ A2q, const __half* __restrict__ B2q,
    const __half* __restrict__ A2k, const __half* __restrict__ B2k,
    const __half* __restrict__ A2v, const __half* __restrict__ B2v,
    __half* __restrict__ Q2, __half* __restrict__ K2h, __half* __restrict__ Vth,
    const float* __restrict__ rc, const float* __restrict__ rs)
{
    extern __shared__ __half sh[];
    uint32_t shBase = smem_u32(sh);
    const int tid  = threadIdx.x;
    const int lane = tid & 31;
    const int wid  = tid >> 5;
    const int wm   = wid & 1;
    const int wn   = wid >> 1;

    const int bid = blockIdx.x;
    int mode, rowBase, colBase;
    const __half *Ap, *Bp;
    if (bid < 256) {
        mode = 0;
        rowBase = (bid >> 4) * 128;
        colBase = (bid & 15) * 128;
        Ap = A2q; Bp = B2q;
    } else if (bid < 320) {
        mode = 1;
        int b = bid - 256;
        rowBase = (b >> 2) * 128;
        colBase = (b & 3) * 128;
        Ap = A2k; Bp = B2k;
    } else {
        mode = 2;
        int b = bid - 320;
        rowBase = (b >> 2) * 128;
        colBase = (b & 3) * 128;
        Ap = A2v; Bp = B2v;
    }

    float acc[4][8][4];
    #pragma unroll
    for (int i = 0; i < 4; i++)
        #pragma unroll
        for (int j = 0; j < 8; j++)
            #pragma unroll
            for (int q = 0; q < 4; q++) acc[i][j][q] = 0.0f;

    gemm_mainloop(shBase, Ap + (size_t)rowBase * KA2, Bp + (size_t)colBase * KDIM,
                  tid, lane, wm, wn, acc, KA2 / 64, KA2, 31);

    #pragma unroll
    for (int fm = 0; fm < 4; fm++) {
        #pragma unroll
        for (int fn = 0; fn < 8; fn++) {
            int r0 = rowBase + wm * 64 + fm * 16 + (lane >> 2);
            int c0 = colBase + wn * 64 + fn * 8 + (lane & 3) * 2;
            float a0 = acc[fm][fn][0], a1 = acc[fm][fn][1];
            float a2 = acc[fm][fn][2], a3 = acc[fm][fn][3];
            if (mode == 2) {
                Vth[(size_t)c0 * T_SEQ + r0]           = __float2half(a0);
                Vth[(size_t)(c0 + 1) * T_SEQ + r0]     = __float2half(a1);
                Vth[(size_t)c0 * T_SEQ + r0 + 8]       = __float2half(a2);
                Vth[(size_t)(c0 + 1) * T_SEQ + r0 + 8] = __float2half(a3);
            } else {
                const int h = c0 >> 6;
                const int d = c0 & 63;
                const int i = d >> 1;
                float c1 = rc[r0 * 32 + i],       s1 = rs[r0 * 32 + i];
                float c2 = rc[(r0 + 8) * 32 + i], s2 = rs[(r0 + 8) * 32 + i];
                float y0 = a0 * c1 - a1 * s1, y1 = a0 * s1 + a1 * c1;
                float y2 = a2 * c2 - a3 * s2, y3 = a2 * s2 + a3 * c2;
                __half h0 = __float2half(y0), h1 = __float2half(y1);
                __half h2 = __float2half(y2), h3 = __float2half(y3);
                if (mode == 0) {
                    size_t b0 = ((size_t)h * T_SEQ + r0) * 128 + d;
                    size_t b8 = b0 + 8 * 128;
                    *reinterpret_cast<uint32_t*>(Q2 + b0) = pack_h2(h0, h1);
                    *reinterpret_cast<uint32_t*>(Q2 + b8) = pack_h2(h2, h3);
                    *reinterpret_cast<uint32_t*>(Q2 + b0 + 64) = pack_h2(
                        __float2half(y0 - __half2float(h0)),
                        __float2half(y1 - __half2float(h1)));
                    *reinterpret_cast<uint32_t*>(Q2 + b8 + 64) = pack_h2(
                        __float2half(y2 - __half2float(h2)),
                        __float2half(y3 - __half2float(h3)));
                } else {
                    size_t b0 = ((size_t)h * T_SEQ + r0) * 64 + d;
                    size_t b8 = b0 + 8 * 64;
                    *reinterpret_cast<uint32_t*>(K2h + b0) = pack_h2(h0, h1);
                    *reinterpret_cast<uint32_t*>(K2h + b8) = pack_h2(h2, h3);
                }
            }
        }
    }
}

// O-projection GEMM: A = Aoh [T,2048] hi-only fp16 -> K = 2048 (half the work)
__global__ __launch_bounds__(128, 2) void gemm_o_kernel(
    const __half* __restrict__ Aoh, const __half* __restrict__ B2,
    float* __restrict__ C)
{
    extern __shared__ __half sh[];
    uint32_t shBase = smem_u32(sh);
    const int tid  = threadIdx.x;
    const int lane = tid & 31;
    const int wid  = tid >> 5;
    const int wm   = wid & 1;
    const int wn   = wid >> 1;
    const int rowBase = blockIdx.y * 128;
    const int colBase = blockIdx.x * 128;

    float acc[4][8][4];
    #pragma unroll
    for (int i = 0; i < 4; i++)
        #pragma unroll
        for (int j = 0; j < 8; j++)
            #pragma unroll
            for (int q = 0; q < 4; q++) acc[i][j][q] = 0.0f;

    gemm_mainloop(shBase, Aoh + (size_t)rowBase * KDIM, B2 + (size_t)colBase * KDIM,
                  tid, lane, wm, wn, acc, KDIM / 64, KDIM, 63);

    #pragma unroll
    for (int fm = 0; fm < 4; fm++) {
        #pragma unroll
        for (int fn = 0; fn < 8; fn++) {
            int r0 = rowBase + wm * 64 + fm * 16 + (lane >> 2);
            int c0 = colBase + wn * 64 + fn * 8 + (lane & 3) * 2;
            *reinterpret_cast<float2*>(&C[(size_t)r0 * D_MODEL + c0]) =
                make_float2(acc[fm][fn][0], acc[fm][fn][1]);
            *reinterpret_cast<float2*>(&C[(size_t)(r0 + 8) * D_MODEL + c0]) =
                make_float2(acc[fm][fn][2], acc[fm][fn][3]);
        }
    }
}

// ---------------------------------------------------------------------------
// HMMA flash attention (128 threads). P·V now single-term (Ph only).
// Output written hi-only to Aoh [T, 2048].
// ---------------------------------------------------------------------------
#define FLASH_SMEM_BYTES ((128 * QPAD + 64 * KVPAD + 64 * KVPAD) * 2)

__global__ __launch_bounds__(128) void flash_hmma_kernel(
    const __half* __restrict__ Q2,
    const __half* __restrict__ K2h,
    const __half* __restrict__ Vth,
    __half* __restrict__ Aoh)
{
    extern __shared__ __half fs[];
    const uint32_t QsA = smem_u32(fs);
    const uint32_t KsA = QsA + 128 * QPAD * 2;
    const uint32_t VsA = KsA + 64 * KVPAD * 2;

    const int tid = threadIdx.x, lane = tid & 31, wq = tid >> 5;
    const int h = blockIdx.y, kvh = h >> 2;
    const int m0 = (gridDim.x - 1 - (int)blockIdx.x) * 128;

    const int g  = lane >> 2;
    const int tg = lane & 3;
    const int lrow = (lane & 7) + ((lane >> 3) & 1) * 8;
    const int lcol = (lane >> 4) * 8;
    const float NEG = -1e30f;
    const float scale = 0.125f;

    {
        const __half* Qg = Q2 + ((size_t)h * T_SEQ + m0) * 128;
        #pragma unroll
        for (int u = 0; u < 16; u++) {
            int id = tid + u * 128;
            int row = id >> 4, c = id & 15;
            cp_async16(QsA + (uint32_t)(row * QPAD + c * 8) * 2,
                       Qg + (size_t)row * 128 + c * 8);
        }
        CP_COMMIT();
    }

    float o[2][8][4];
    #pragma unroll
    for (int i = 0; i < 2; i++)
        #pragma unroll
        for (int j = 0; j < 8; j++)
            #pragma unroll
            for (int q = 0; q < 4; q++) o[i][j][q] = 0.0f;
    float mrow[2][2] = {{NEG, NEG}, {NEG, NEG}};
    float lacc[2][2] = {{0.f, 0.f}, {0.f, 0.f}};

    const int nT = m0 / 64 + 2;
    for (int jt = 0; jt < nT; jt++) {
        const int j0 = jt * 64;
        __syncthreads();
        #pragma unroll
        for (int u = 0; u < 4; u++) {
            int id = tid + u * 128;
            int row = id >> 3, c = id & 7;
            cp_async16(KsA + (uint32_t)(row * KVPAD + c * 8) * 2,
                       K2h + ((size_t)kvh * T_SEQ + j0 + row) * 64 + c * 8);
        }
        #pragma unroll
        for (int u = 0; u < 4; u++) {
            int id = tid + u * 128;
            int row = id >> 3, c = id & 7;
            cp_async16(VsA + (uint32_t)(row * KVPAD + c * 8) * 2,
                       Vth + (size_t)(kvh * 64 + row) * T_SEQ + j0 + c * 8);
        }
        CP_COMMIT();
        CP_WAIT(0);
        __syncthreads();

        float s[2][8][4];
        #pragma unroll
        for (int i = 0; i < 2; i++)
            #pragma unroll
            for (int j = 0; j < 8; j++)
                #pragma unroll
                for (int q = 0; q < 4; q++) s[i][j][q] = 0.0f;

        #pragma unroll
        for (int kc = 0; kc < 8; kc++) {
            uint32_t af[2][4], bk[4][4];
            #pragma unroll
            for (int fm = 0; fm < 2; fm++)
                ldmatrix_x4(af[fm][0], af[fm][1], af[fm][2], af[fm][3],
                    QsA + (uint32_t)((wq * 32 + fm * 16 + lrow) * QPAD + kc * 16 + lcol) * 2);
            #pragma unroll
            for (int fp = 0; fp < 4; fp++)
                ldmatrix_x4(bk[fp][0], bk[fp][1], bk[fp][2], bk[fp][3],
                    KsA + (uint32_t)((fp * 16 + lrow) * KVPAD + (kc & 3) * 16 + lcol) * 2);
            #pragma unroll
            for (int fm = 0; fm < 2; fm++)
                #pragma unroll
                for (int fn = 0; fn < 8; fn++) {
                    uint32_t b0 = (fn & 1) ? bk[fn >> 1][1] : bk[fn >> 1][0];
                    uint32_t b1 = (fn & 1) ? bk[fn >> 1][3] : bk[fn >> 1][2];
                    mma16816(s[fm][fn], af[fm], b0, b1);
                }
        }

        #pragma unroll
        for (int fm = 0; fm < 2; fm++) {
            const int r0 = m0 + wq * 32 + fm * 16 + g;
            const int r1 = r0 + 8;
            float mx0 = NEG, mx1 = NEG;
            #pragma unroll
            for (int fn = 0; fn < 8; fn++) {
                const int cb = j0 + fn * 8 + tg * 2;
                float v0 = (cb     <= r0) ? s[fm][fn][0] * scale : NEG;
                float v1 = (cb + 1 <= r0) ? s[fm][fn][1] * scale : NEG;
                float v2 = (cb     <= r1) ? s[fm][fn][2] * scale : NEG;
                float v3 = (cb + 1 <= r1) ? s[fm][fn][3] * scale : NEG;
                s[fm][fn][0] = v0; s[fm][fn][1] = v1;
                s[fm][fn][2] = v2; s[fm][fn][3] = v3;
                mx0 = fmaxf(mx0, fmaxf(v0, v1));
                mx1 = fmaxf(mx1, fmaxf(v2, v3));
            }
            mx0 = fmaxf(mx0, __shfl_xor_sync(0xffffffffu, mx0, 1));
            mx0 = fmaxf(mx0, __shfl_xor_sync(0xffffffffu, mx0, 2));
            mx1 = fmaxf(mx1, __shfl_xor_sync(0xffffffffu, mx1, 1));
            mx1 = fmaxf(mx1, __shfl_xor_sync(0xffffffffu, mx1, 2));
            const float mn0 = fmaxf(mrow[fm][0], mx0);
            const float mn1 = fmaxf(mrow[fm][1], mx1);
            const float c0 = __expf(mrow[fm][0] - mn0);
            const float c1 = __expf(mrow[fm][1] - mn1);
            mrow[fm][0] = mn0; mrow[fm][1] = mn1;
            float ls0 = 0.f, ls1 = 0.f;
            #pragma unroll
            for (int fn = 0; fn < 8; fn++) {
                float p0 = __expf(s[fm][fn][0] - mn0);
                float p1 = __expf(s[fm][fn][1] - mn0);
                float p2 = __expf(s[fm][fn][2] - mn1);
                float p3 = __expf(s[fm][fn][3] - mn1);
                s[fm][fn][0] = p0; s[fm][fn][1] = p1;
                s[fm][fn][2] = p2; s[fm][fn][3] = p3;
                ls0 += p0 + p1; ls1 += p2 + p3;
                o[fm][fn][0] *= c0; o[fm][fn][1] *= c0;
                o[fm][fn][2] *= c1; o[fm][fn][3] *= c1;
            }
            lacc[fm][0] = lacc[fm][0] * c0 + ls0;
            lacc[fm][1] = lacc[fm][1] * c1 + ls1;
        }

        // O += Ph·Vh (single-term)
        #pragma unroll
        for (int kc2 = 0; kc2 < 4; kc2++) {
            uint32_t aPh[2][4];
            #pragma unroll
            for (int fm = 0; fm < 2; fm++) {
                #pragma unroll
                for (int half = 0; half < 2; half++) {
                    const int fr = 2 * kc2 + half;
                    aPh[fm][half * 2 + 0] = pack_h2(
                        __float2half(s[fm][fr][0]), __float2half(s[fm][fr][1]));
                    aPh[fm][half * 2 + 1] = pack_h2(
                        __float2half(s[fm][fr][2]), __float2half(s[fm][fr][3]));
                }
            }
            uint32_t bv[4][4];
            #pragma unroll
            for (int fp = 0; fp < 4; fp++)
                ldmatrix_x4(bv[fp][0], bv[fp][1], bv[fp][2], bv[fp][3],
                    VsA + (uint32_t)((fp * 16 + lrow) * KVPAD + kc2 * 16 + lcol) * 2);
            #pragma unroll
            for (int fm = 0; fm < 2; fm++)
                #pragma unroll
                for (int fn = 0; fn < 8; fn++) {
                    uint32_t b0 = (fn & 1) ? bv[fn >> 1][1] : bv[fn >> 1][0];
                    uint32_t b1 = (fn & 1) ? bv[fn >> 1][3] : bv[fn >> 1][2];
                    mma16816(o[fm][fn], aPh[fm], b0, b1);
                }
        }
    }

    float linv[2][2];
    #pragma unroll
    for (int fm = 0; fm < 2; fm++)
        #pragma unroll
        for (int half = 0; half < 2; half++) {
            float lv = lacc[fm][half];
            lv += __shfl_xor_sync(0xffffffffu, lv, 1);
            lv += __shfl_xor_sync(0xffffffffu, lv, 2);
            linv[fm][half] = 1.0f / lv;
        }
    #pragma unroll
    for (int fm = 0; fm < 2; fm++) {
        const int r0 = m0 + wq * 32 + fm * 16 + g;
        #pragma unroll
        for (int fn = 0; fn < 8; fn++) {
            const int col = h * HD + fn * 8 + tg * 2;
            float y0 = o[fm][fn][0] * linv[fm][0];
            float y1 = o[fm][fn][1] * linv[fm][0];
            float y2 = o[fm][fn][2] * linv[fm][1];
            float y3 = o[fm][fn][3] * linv[fm][1];
            size_t b0 = (size_t)r0 * KDIM + col;
            size_t b8 = b0 + 8 * KDIM;
            *reinterpret_cast<uint32_t*>(Aoh + b0) =
                pack_h2(__float2half(y0), __float2half(y1));
            *reinterpret_cast<uint32_t*>(Aoh + b8) =
                pack_h2(__float2half(y2), __float2half(y3));
        }
    }
}

// ---------------------------------------------------------------------------
// Launch
// ---------------------------------------------------------------------------
extern "C" void kernel_launch(void* const* d_in, const int* in_sizes, int n_in,
                              void* d_out, int out_size)
{
    const float *q_embs, *k_embs, *v_embs, *w_q, *w_k, *w_v, *w_o;
    if (in_sizes[3] == D_MODEL * DIM_KV) {
        k_embs = (const float*)d_in[0];
        q_embs = (const float*)d_in[1];
        v_embs = (const float*)d_in[2];
        w_k    = (const float*)d_in[3];
        w_o    = (const float*)d_in[4];
        w_q    = (const float*)d_in[5];
        w_v    = (const float*)d_in[6];
    } else {
        q_embs = (const float*)d_in[0];
        k_embs = (const float*)d_in[1];
        v_embs = (const float*)d_in[2];
        w_q    = (const float*)d_in[3];
        w_k    = (const float*)d_in[4];
        w_v    = (const float*)d_in[5];
        w_o    = (const float*)d_in[6];
    }
    float* out = (float*)d_out;

    float *RC, *RS;
    __half *A2q, *A2k, *A2v, *Aoh, *B2q, *B2k, *B2v, *B2o, *Q2, *K2h, *Vth;
    cudaGetSymbolAddress((void**)&A2q, g_A2q);
    cudaGetSymbolAddress((void**)&A2k, g_A2k);
    cudaGetSymbolAddress((void**)&A2v, g_A2v);
    cudaGetSymbolAddress((void**)&Aoh, g_Aoh);
    cudaGetSymbolAddress((void**)&B2q, g_B2q);
    cudaGetSymbolAddress((void**)&B2k, g_B2k);
    cudaGetSymbolAddress((void**)&B2v, g_B2v);
    cudaGetSymbolAddress((void**)&B2o, g_B2o);
    cudaGetSymbolAddress((void**)&Q2,  g_Q2);
    cudaGetSymbolAddress((void**)&K2h, g_K2h);
    cudaGetSymbolAddress((void**)&Vth, g_Vth);
    cudaGetSymbolAddress((void**)&RC,  g_rc);
    cudaGetSymbolAddress((void**)&RS,  g_rs);

    cudaFuncSetAttribute(gemm_uber_kernel,
                         cudaFuncAttributeMaxDynamicSharedMemorySize, GEMM_SMEM_BYTES);
    cudaFuncSetAttribute(gemm_o_kernel,
                         cudaFuncAttributeMaxDynamicSharedMemorySize, GEMM_SMEM_BYTES);
    cudaFuncSetAttribute(flash_hmma_kernel,
                         cudaFuncAttributeMaxDynamicSharedMemorySize, FLASH_SMEM_BYTES);

    rope_table_kernel<<<(T_SEQ * 32 + 255) / 256, 256>>>(RC, RS);                 // 1
    split_a3_kernel<<<dim3((T_SEQ * (KDIM / 4) + 255) / 256, 1, 3), 256>>>(
        q_embs, k_embs, v_embs, A2q, A2k, A2v);                                   // 2
    split_b4_kernel<<<dim3(D_MODEL / 32, KDIM / 32, 4), dim3(32, 8)>>>(
        w_q, w_k, w_v, w_o, B2q, B2k, B2v, B2o);                                  // 3

    gemm_uber_kernel<<<384, 128, GEMM_SMEM_BYTES>>>(
        A2q, B2q, A2k, B2k, A2v, B2v, Q2, K2h, Vth, RC, RS);                      // 4 (profile slot)

    flash_hmma_kernel<<<dim3(T_SEQ / 128, NQH), 128, FLASH_SMEM_BYTES>>>(
        Q2, K2h, Vth, Aoh);                                                       // 5

    gemm_o_kernel<<<dim3(D_MODEL / 128, T_SEQ / 128), 128, GEMM_SMEM_BYTES>>>(
        Aoh, B2o, out);                                                           // 6
}

// round 16
// speedup vs baseline: 1.6906x; 1.2565x over previous
#include <cuda_runtime.h>
#include <cuda_bf16.h>
#include <cuda_fp16.h>
#include <math.h>
#include <stdint.h>

#define D_MODEL 2048
#define T_SEQ   2048
#define NQH     32
#define NKVH    8
#define HD      64
#define DIM_KV  512
#define KDIM    2048
#define PADH    72             // GEMM smem row stride (halves)
#define QPAD    136            // flash Q smem row stride (halves)
#define KVPAD   72             // flash K/V smem row stride (halves)

// ---------------------------------------------------------------------------
// Device-global scratch (projection A's now hi-only fp16 [T, 2048])
// ---------------------------------------------------------------------------
__device__ __align__(16) __half g_Ahq[T_SEQ * KDIM];
__device__ __align__(16) __half g_Ahk[T_SEQ * KDIM];
__device__ __align__(16) __half g_Ahv[T_SEQ * KDIM];
__device__ __align__(16) __half g_Aoh[T_SEQ * KDIM];     // flash output, hi only
__device__ __align__(16) __half g_B2q[D_MODEL * KDIM];
__device__ __align__(16) __half g_B2k[DIM_KV  * KDIM];
__device__ __align__(16) __half g_B2v[DIM_KV  * KDIM];
__device__ __align__(16) __half g_B2o[D_MODEL * KDIM];
__device__ __align__(16) __half g_Q2[NQH  * T_SEQ * 128]; // [h][t][Qh|Ql]
__device__ __align__(16) __half g_K2h[NKVH * T_SEQ * 64]; // [kvh][t][Kh]
__device__ __align__(16) __half g_Vth[DIM_KV * T_SEQ];    // V^T hi [d][t]
__device__ float g_rc[T_SEQ * 32];
__device__ float g_rs[T_SEQ * 32];

// ---------------------------------------------------------------------------
// PTX helpers
// ---------------------------------------------------------------------------
__device__ __forceinline__ uint32_t smem_u32(const void* p) {
    uint32_t a;
    asm("{ .reg .u64 t; cvta.to.shared.u64 t, %1; cvt.u32.u64 %0, t; }"
        : "=r"(a) : "l"(p));
    return a;
}

__device__ __forceinline__ void ldmatrix_x4(uint32_t& r0, uint32_t& r1,
                                            uint32_t& r2, uint32_t& r3,
                                            uint32_t addr) {
    asm volatile("ldmatrix.sync.aligned.m8n8.x4.shared.b16 {%0,%1,%2,%3}, [%4];"
                 : "=r"(r0), "=r"(r1), "=r"(r2), "=r"(r3) : "r"(addr));
}

__device__ __forceinline__ void mma16816(float* d, const uint32_t* a,
                                         uint32_t b0, uint32_t b1) {
    asm volatile(
        "mma.sync.aligned.m16n8k16.row.col.f32.f16.f16.f32 "
        "{%0,%1,%2,%3}, {%4,%5,%6,%7}, {%8,%9}, {%0,%1,%2,%3};"
        : "+f"(d[0]), "+f"(d[1]), "+f"(d[2]), "+f"(d[3])
        : "r"(a[0]), "r"(a[1]), "r"(a[2]), "r"(a[3]), "r"(b0), "r"(b1));
}

__device__ __forceinline__ void cp_async16(uint32_t saddr, const void* gaddr) {
    asm volatile("cp.async.cg.shared.global [%0], [%1], 16;"
                 :: "r"(saddr), "l"(gaddr));
}
#define CP_COMMIT() asm volatile("cp.async.commit_group;" ::: "memory")
#define CP_WAIT(n)  asm volatile("cp.async.wait_group %0;" :: "n"(n) : "memory")

__device__ __forceinline__ uint32_t pack_h2(__half a, __half b) {
    return ((uint32_t)__half_as_ushort(b) << 16) | __half_as_ushort(a);
}

// ---------------------------------------------------------------------------
// Conversions
// ---------------------------------------------------------------------------
// hi-only fp32 -> fp16 convert for all three activations
__global__ void conv_a3_kernel(const float* __restrict__ Xq,
                               const float* __restrict__ Xk,
                               const float* __restrict__ Xv,
                               __half* __restrict__ Ahq,
                               __half* __restrict__ Ahk,
                               __half* __restrict__ Ahv)
{
    const float* X = (blockIdx.z == 0) ? Xq : (blockIdx.z == 1) ? Xk : Xv;
    __half* A      = (blockIdx.z == 0) ? Ahq : (blockIdx.z == 1) ? Ahk : Ahv;
    int idx = blockIdx.x * blockDim.x + threadIdx.x;      // one float4 each
    if (idx >= T_SEQ * (KDIM / 4)) return;
    float4 x = *reinterpret_cast<const float4*>(X + (size_t)idx * 4);
    *reinterpret_cast<uint2*>(A + (size_t)idx * 4) = make_uint2(
        pack_h2(__float2half(x.x), __float2half(x.y)),
        pack_h2(__float2half(x.z), __float2half(x.w)));
}

__global__ void split_b4_kernel(const float* __restrict__ Wq,
                                const float* __restrict__ Wk,
                                const float* __restrict__ Wv,
                                const float* __restrict__ Wo,
                                __half* __restrict__ B2q,
                                __half* __restrict__ B2k,
                                __half* __restrict__ B2v,
                                __half* __restrict__ B2o)
{
    const int z = blockIdx.z;
    const float* W = (z == 0) ? Wq : (z == 1) ? Wk : (z == 2) ? Wv : Wo;
    __half* B2     = (z == 0) ? B2q : (z == 1) ? B2k : (z == 2) ? B2v : B2o;
    const int N    = (z == 1 || z == 2) ? DIM_KV : D_MODEL;

    __shared__ float tile[32][33];
    int n0 = blockIdx.x * 32, k0 = blockIdx.y * 32;
    if (n0 >= N) return;
    int tx = threadIdx.x, ty = threadIdx.y;   // 32 x 8
    #pragma unroll
    for (int i = 0; i < 32; i += 8)
        tile[ty + i][tx] = W[(size_t)(k0 + ty + i) * N + n0 + tx];
    __syncthreads();
    int tid = ty * 32 + tx;
    int nl  = tid >> 3;
    int k4  = (tid & 7) * 4;
    __half h0 = __float2half(tile[k4 + 0][nl]);
    __half h1 = __float2half(tile[k4 + 1][nl]);
    __half h2 = __float2half(tile[k4 + 2][nl]);
    __half h3 = __float2half(tile[k4 + 3][nl]);
    *reinterpret_cast<uint2*>(B2 + (size_t)(n0 + nl) * KDIM + k0 + k4) =
        make_uint2(pack_h2(h0, h1), pack_h2(h2, h3));
}

__global__ void rope_table_kernel(float* __restrict__ rc, float* __restrict__ rs)
{
    int idx = blockIdx.x * blockDim.x + threadIdx.x;
    if (idx >= T_SEQ * 32) return;
    int t = idx >> 5, i = idx & 31;
    float invf = (float)pow(500000.0, -(double)i / 32.0);
    float angf = (float)t * invf;
    double ang = (double)angf;
    rc[idx] = (float)cos(ang);
    rs[idx] = (float)sin(ang);
}

// ---------------------------------------------------------------------------
// Shared GEMM mainloop: A [*,2048] fp16, B [*,2048] fp16, K = 2048 (32 chunks)
// ---------------------------------------------------------------------------
#define GEMM_SMEM_BYTES (4 * 128 * PADH * 2)   // 73728

__device__ __forceinline__ void ldgsts_tileS(uint32_t sBase, const __half* G,
                                             int k0, int tid)
{
    #pragma unroll
    for (int i = 0; i < 8; i++) {
        int id  = tid + (i << 7);
        int row = id >> 3;
        int c8  = id & 7;
        cp_async16(sBase + (uint32_t)(row * PADH + c8 * 8) * 2,
                   G + (size_t)row * KDIM + k0 + c8 * 8);
    }
}

__device__ __forceinline__ void gemm_mainloop(
    uint32_t shBase, const __half* Ag, const __half* Bg,
    int tid, int lane, int wm, int wn, float acc[4][8][4])
{
    const uint32_t TILE_B = 128 * PADH * 2;
    const int nCh = KDIM / 64;   // 32

    ldgsts_tileS(shBase + 0 * TILE_B, Ag, 0, tid);
    ldgsts_tileS(shBase + 2 * TILE_B, Bg, 0, tid);
    CP_COMMIT();

    const int lrow = (lane & 7) + ((lane >> 3) & 1) * 8;
    const int lcol = (lane >> 4) * 8;

    for (int c = 0; c < nCh; c++) {
        const int s = c & 1;
        if (c + 1 < nCh) {
            const int s2 = s ^ 1;
            ldgsts_tileS(shBase + s2 * TILE_B,       Ag, (c + 1) * 64, tid);
            ldgsts_tileS(shBase + (2 + s2) * TILE_B, Bg, (c + 1) * 64, tid);
            CP_COMMIT();
            CP_WAIT(1);
        } else {
            CP_WAIT(0);
        }
        __syncthreads();

        const uint32_t aB = shBase + s * TILE_B;
        const uint32_t bB = shBase + (2 + s) * TILE_B;
        #pragma unroll
        for (int ks = 0; ks < 4; ks++) {
            const int k16 = ks * 16;
            uint32_t af[4][4], bfr[4][4];
            #pragma unroll
            for (int fm = 0; fm < 4; fm++)
                ldmatrix_x4(af[fm][0], af[fm][1], af[fm][2], af[fm][3],
                    aB + (uint32_t)((wm * 64 + fm * 16 + lrow) * PADH + k16 + lcol) * 2);
            #pragma unroll
            for (int fp = 0; fp < 4; fp++)
                ldmatrix_x4(bfr[fp][0], bfr[fp][1], bfr[fp][2], bfr[fp][3],
                    bB + (uint32_t)((wn * 64 + fp * 16 + lrow) * PADH + k16 + lcol) * 2);
            #pragma unroll
            for (int fm = 0; fm < 4; fm++)
                #pragma unroll
                for (int fn = 0; fn < 8; fn++) {
                    uint32_t b0 = (fn & 1) ? bfr[fn >> 1][1] : bfr[fn >> 1][0];
                    uint32_t b1 = (fn & 1) ? bfr[fn >> 1][3] : bfr[fn >> 1][2];
                    mma16816(acc[fm][fn], af[fm], b0, b1);
                }
        }
        __syncthreads();
    }
}

// ---------------------------------------------------------------------------
// Uber projection kernel: Q (256 CTAs) + K (64) + V (64), all K=2048 hi-only A.
// ---------------------------------------------------------------------------
__global__ __launch_bounds__(128, 2) void gemm_uber_kernel(
    const __half* __restrict__ Ahq, const __half* __restrict__ B2q,
    const __half* __restrict__ Ahk, const __half* __restrict__ B2k,
    const __half* __restrict__ Ahv, const __half* __restrict__ B2v,
    __half* __restrict__ Q2, __half* __restrict__ K2h, __half* __restrict__ Vth,
    const float* __restrict__ rc, const float* __restrict__ rs)
{
    extern __shared__ __half sh[];
    uint32_t shBase = smem_u32(sh);
    const int tid  = threadIdx.x;
    const int lane = tid & 31;
    const int wid  = tid >> 5;
    const int wm   = wid & 1;
    const int wn   = wid >> 1;

    const int bid = blockIdx.x;
    int mode, rowBase, colBase;
    const __half *Ap, *Bp;
    if (bid < 256) {
        mode = 0;
        rowBase = (bid >> 4) * 128;
        colBase = (bid & 15) * 128;
        Ap = Ahq; Bp = B2q;
    } else if (bid < 320) {
        mode = 1;
        int b = bid - 256;
        rowBase = (b >> 2) * 128;
        colBase = (b & 3) * 128;
        Ap = Ahk; Bp = B2k;
    } else {
        mode = 2;
        int b = bid - 320;
        rowBase = (b >> 2) * 128;
        colBase = (b & 3) * 128;
        Ap = Ahv; Bp = B2v;
    }

    float acc[4][8][4];
    #pragma unroll
    for (int i = 0; i < 4; i++)
        #pragma unroll
        for (int j = 0; j < 8; j++)
            #pragma unroll
            for (int q = 0; q < 4; q++) acc[i][j][q] = 0.0f;

    gemm_mainloop(shBase, Ap + (size_t)rowBase * KDIM, Bp + (size_t)colBase * KDIM,
                  tid, lane, wm, wn, acc);

    #pragma unroll
    for (int fm = 0; fm < 4; fm++) {
        #pragma unroll
        for (int fn = 0; fn < 8; fn++) {
            int r0 = rowBase + wm * 64 + fm * 16 + (lane >> 2);
            int c0 = colBase + wn * 64 + fn * 8 + (lane & 3) * 2;
            float a0 = acc[fm][fn][0], a1 = acc[fm][fn][1];
            float a2 = acc[fm][fn][2], a3 = acc[fm][fn][3];
            if (mode == 2) {
                Vth[(size_t)c0 * T_SEQ + r0]           = __float2half(a0);
                Vth[(size_t)(c0 + 1) * T_SEQ + r0]     = __float2half(a1);
                Vth[(size_t)c0 * T_SEQ + r0 + 8]       = __float2half(a2);
                Vth[(size_t)(c0 + 1) * T_SEQ + r0 + 8] = __float2half(a3);
            } else {
                const int h = c0 >> 6;
                const int d = c0 & 63;
                const int i = d >> 1;
                float c1 = rc[r0 * 32 + i],       s1 = rs[r0 * 32 + i];
                float c2 = rc[(r0 + 8) * 32 + i], s2 = rs[(r0 + 8) * 32 + i];
                float y0 = a0 * c1 - a1 * s1, y1 = a0 * s1 + a1 * c1;
                float y2 = a2 * c2 - a3 * s2, y3 = a2 * s2 + a3 * c2;
                __half h0 = __float2half(y0), h1 = __float2half(y1);
                __half h2 = __float2half(y2), h3 = __float2half(y3);
                if (mode == 0) {
                    size_t b0 = ((size_t)h * T_SEQ + r0) * 128 + d;
                    size_t b8 = b0 + 8 * 128;
                    *reinterpret_cast<uint32_t*>(Q2 + b0) = pack_h2(h0, h1);
                    *reinterpret_cast<uint32_t*>(Q2 + b8) = pack_h2(h2, h3);
                    *reinterpret_cast<uint32_t*>(Q2 + b0 + 64) = pack_h2(
                        __float2half(y0 - __half2float(h0)),
                        __float2half(y1 - __half2float(h1)));
                    *reinterpret_cast<uint32_t*>(Q2 + b8 + 64) = pack_h2(
                        __float2half(y2 - __half2float(h2)),
                        __float2half(y3 - __half2float(h3)));
                } else {
                    size_t b0 = ((size_t)h * T_SEQ + r0) * 64 + d;
                    size_t b8 = b0 + 8 * 64;
                    *reinterpret_cast<uint32_t*>(K2h + b0) = pack_h2(h0, h1);
                    *reinterpret_cast<uint32_t*>(K2h + b8) = pack_h2(h2, h3);
                }
            }
        }
    }
}

// O-projection GEMM (hi-only A, K=2048, fp32 store)
__global__ __launch_bounds__(128, 2) void gemm_o_kernel(
    const __half* __restrict__ Aoh, const __half* __restrict__ B2,
    float* __restrict__ C)
{
    extern __shared__ __half sh[];
    uint32_t shBase = smem_u32(sh);
    const int tid  = threadIdx.x;
    const int lane = tid & 31;
    const int wid  = tid >> 5;
    const int wm   = wid & 1;
    const int wn   = wid >> 1;
    const int rowBase = blockIdx.y * 128;
    const int colBase = blockIdx.x * 128;

    float acc[4][8][4];
    #pragma unroll
    for (int i = 0; i < 4; i++)
        #pragma unroll
        for (int j = 0; j < 8; j++)
            #pragma unroll
            for (int q = 0; q < 4; q++) acc[i][j][q] = 0.0f;

    gemm_mainloop(shBase, Aoh + (size_t)rowBase * KDIM, B2 + (size_t)colBase * KDIM,
                  tid, lane, wm, wn, acc);

    #pragma unroll
    for (int fm = 0; fm < 4; fm++) {
        #pragma unroll
        for (int fn = 0; fn < 8; fn++) {
            int r0 = rowBase + wm * 64 + fm * 16 + (lane >> 2);
            int c0 = colBase + wn * 64 + fn * 8 + (lane & 3) * 2;
            *reinterpret_cast<float2*>(&C[(size_t)r0 * D_MODEL + c0]) =
                make_float2(acc[fm][fn][0], acc[fm][fn][1]);
            *reinterpret_cast<float2*>(&C[(size_t)(r0 + 8) * D_MODEL + c0]) =
                make_float2(acc[fm][fn][2], acc[fm][fn][3]);
        }
    }
}

// ---------------------------------------------------------------------------
// HMMA flash attention (128 threads). S 2-term Q; P·V single-term.
// Output hi-only to Aoh [T, 2048].
// ---------------------------------------------------------------------------
#define FLASH_SMEM_BYTES ((128 * QPAD + 64 * KVPAD + 64 * KVPAD) * 2)

__global__ __launch_bounds__(128) void flash_hmma_kernel(
    const __half* __restrict__ Q2,
    const __half* __restrict__ K2h,
    const __half* __restrict__ Vth,
    __half* __restrict__ Aoh)
{
    extern __shared__ __half fs[];
    const uint32_t QsA = smem_u32(fs);
    const uint32_t KsA = QsA + 128 * QPAD * 2;
    const uint32_t VsA = KsA + 64 * KVPAD * 2;

    const int tid = threadIdx.x, lane = tid & 31, wq = tid >> 5;
    const int h = blockIdx.y, kvh = h >> 2;
    const int m0 = (gridDim.x - 1 - (int)blockIdx.x) * 128;

    const int g  = lane >> 2;
    const int tg = lane & 3;
    const int lrow = (lane & 7) + ((lane >> 3) & 1) * 8;
    const int lcol = (lane >> 4) * 8;
    const float NEG = -1e30f;
    const float scale = 0.125f;

    {
        const __half* Qg = Q2 + ((size_t)h * T_SEQ + m0) * 128;
        #pragma unroll
        for (int u = 0; u < 16; u++) {
            int id = tid + u * 128;
            int row = id >> 4, c = id & 15;
            cp_async16(QsA + (uint32_t)(row * QPAD + c * 8) * 2,
                       Qg + (size_t)row * 128 + c * 8);
        }
        CP_COMMIT();
    }

    float o[2][8][4];
    #pragma unroll
    for (int i = 0; i < 2; i++)
        #pragma unroll
        for (int j = 0; j < 8; j++)
            #pragma unroll
            for (int q = 0; q < 4; q++) o[i][j][q] = 0.0f;
    float mrow[2][2] = {{NEG, NEG}, {NEG, NEG}};
    float lacc[2][2] = {{0.f, 0.f}, {0.f, 0.f}};

    const int nT = m0 / 64 + 2;
    for (int jt = 0; jt < nT; jt++) {
        const int j0 = jt * 64;
        __syncthreads();
        #pragma unroll
        for (int u = 0; u < 4; u++) {
            int id = tid + u * 128;
            int row = id >> 3, c = id & 7;
            cp_async16(KsA + (uint32_t)(row * KVPAD + c * 8) * 2,
                       K2h + ((size_t)kvh * T_SEQ + j0 + row) * 64 + c * 8);
        }
        #pragma unroll
        for (int u = 0; u < 4; u++) {
            int id = tid + u * 128;
            int row = id >> 3, c = id & 7;
            cp_async16(VsA + (uint32_t)(row * KVPAD + c * 8) * 2,
                       Vth + (size_t)(kvh * 64 + row) * T_SEQ + j0 + c * 8);
        }
        CP_COMMIT();
        CP_WAIT(0);
        __syncthreads();

        float s[2][8][4];
        #pragma unroll
        for (int i = 0; i < 2; i++)
            #pragma unroll
            for (int j = 0; j < 8; j++)
                #pragma unroll
                for (int q = 0; q < 4; q++) s[i][j][q] = 0.0f;

        #pragma unroll
        for (int kc = 0; kc < 8; kc++) {
            uint32_t af[2][4], bk[4][4];
            #pragma unroll
            for (int fm = 0; fm < 2; fm++)
                ldmatrix_x4(af[fm][0], af[fm][1], af[fm][2], af[fm][3],
                    QsA + (uint32_t)((wq * 32 + fm * 16 + lrow) * QPAD + kc * 16 + lcol) * 2);
            #pragma unroll
            for (int fp = 0; fp < 4; fp++)
                ldmatrix_x4(bk[fp][0], bk[fp][1], bk[fp][2], bk[fp][3],
                    KsA + (uint32_t)((fp * 16 + lrow) * KVPAD + (kc & 3) * 16 + lcol) * 2);
            #pragma unroll
            for (int fm = 0; fm < 2; fm++)
                #pragma unroll
                for (int fn = 0; fn < 8; fn++) {
                    uint32_t b0 = (fn & 1) ? bk[fn >> 1][1] : bk[fn >> 1][0];
                    uint32_t b1 = (fn & 1) ? bk[fn >> 1][3] : bk[fn >> 1][2];
                    mma16816(s[fm][fn], af[fm], b0, b1);
                }
        }

        #pragma unroll
        for (int fm = 0; fm < 2; fm++) {
            const int r0 = m0 + wq * 32 + fm * 16 + g;
            const int r1 = r0 + 8;
            float mx0 = NEG, mx1 = NEG;
            #pragma unroll
            for (int fn = 0; fn < 8; fn++) {
                const int cb = j0 + fn * 8 + tg * 2;
                float v0 = (cb     <= r0) ? s[fm][fn][0] * scale : NEG;
                float v1 = (cb + 1 <= r0) ? s[fm][fn][1] * scale : NEG;
                float v2 = (cb     <= r1) ? s[fm][fn][2] * scale : NEG;
                float v3 = (cb + 1 <= r1) ? s[fm][fn][3] * scale : NEG;
                s[fm][fn][0] = v0; s[fm][fn][1] = v1;
                s[fm][fn][2] = v2; s[fm][fn][3] = v3;
                mx0 = fmaxf(mx0, fmaxf(v0, v1));
                mx1 = fmaxf(mx1, fmaxf(v2, v3));
            }
            mx0 = fmaxf(mx0, __shfl_xor_sync(0xffffffffu, mx0, 1));
            mx0 = fmaxf(mx0, __shfl_xor_sync(0xffffffffu, mx0, 2));
            mx1 = fmaxf(mx1, __shfl_xor_sync(0xffffffffu, mx1, 1));
            mx1 = fmaxf(mx1, __shfl_xor_sync(0xffffffffu, mx1, 2));
            const float mn0 = fmaxf(mrow[fm][0], mx0);
            const float mn1 = fmaxf(mrow[fm][1], mx1);
            const float c0 = __expf(mrow[fm][0] - mn0);
            const float c1 = __expf(mrow[fm][1] - mn1);
            mrow[fm][0] = mn0; mrow[fm][1] = mn1;
            float ls0 = 0.f, ls1 = 0.f;
            #pragma unroll
            for (int fn = 0; fn < 8; fn++) {
                float p0 = __expf(s[fm][fn][0] - mn0);
                float p1 = __expf(s[fm][fn][1] - mn0);
                float p2 = __expf(s[fm][fn][2] - mn1);
                float p3 = __expf(s[fm][fn][3] - mn1);
                s[fm][fn][0] = p0; s[fm][fn][1] = p1;
                s[fm][fn][2] = p2; s[fm][fn][3] = p3;
                ls0 += p0 + p1; ls1 += p2 + p3;
                o[fm][fn][0] *= c0; o[fm][fn][1] *= c0;
                o[fm][fn][2] *= c1; o[fm][fn][3] *= c1;
            }
            lacc[fm][0] = lacc[fm][0] * c0 + ls0;
            lacc[fm][1] = lacc[fm][1] * c1 + ls1;
        }

        // O += Ph·Vh
        #pragma unroll
        for (int kc2 = 0; kc2 < 4; kc2++) {
            uint32_t aPh[2][4];
            #pragma unroll
            for (int fm = 0; fm < 2; fm++) {
                #pragma unroll
                for (int half = 0; half < 2; half++) {
                    const int fr = 2 * kc2 + half;
                    aPh[fm][half * 2 + 0] = pack_h2(
                        __float2half(s[fm][fr][0]), __float2half(s[fm][fr][1]));
                    aPh[fm][half * 2 + 1] = pack_h2(
                        __float2half(s[fm][fr][2]), __float2half(s[fm][fr][3]));
                }
            }
            uint32_t bv[4][4];
            #pragma unroll
            for (int fp = 0; fp < 4; fp++)
                ldmatrix_x4(bv[fp][0], bv[fp][1], bv[fp][2], bv[fp][3],
                    VsA + (uint32_t)((fp * 16 + lrow) * KVPAD + kc2 * 16 + lcol) * 2);
            #pragma unroll
            for (int fm = 0; fm < 2; fm++)
                #pragma unroll
                for (int fn = 0; fn < 8; fn++) {
                    uint32_t b0 = (fn & 1) ? bv[fn >> 1][1] : bv[fn >> 1][0];
                    uint32_t b1 = (fn & 1) ? bv[fn >> 1][3] : bv[fn >> 1][2];
                    mma16816(o[fm][fn], aPh[fm], b0, b1);
                }
        }
    }

    float linv[2][2];
    #pragma unroll
    for (int fm = 0; fm < 2; fm++)
        #pragma unroll
        for (int half = 0; half < 2; half++) {
            float lv = lacc[fm][half];
            lv += __shfl_xor_sync(0xffffffffu, lv, 1);
            lv += __shfl_xor_sync(0xffffffffu, lv, 2);
            linv[fm][half] = 1.0f / lv;
        }
    #pragma unroll
    for (int fm = 0; fm < 2; fm++) {
        const int r0 = m0 + wq * 32 + fm * 16 + g;
        #pragma unroll
        for (int fn = 0; fn < 8; fn++) {
            const int col = h * HD + fn * 8 + tg * 2;
            float y0 = o[fm][fn][0] * linv[fm][0];
            float y1 = o[fm][fn][1] * linv[fm][0];
            float y2 = o[fm][fn][2] * linv[fm][1];
            float y3 = o[fm][fn][3] * linv[fm][1];
            size_t b0 = (size_t)r0 * KDIM + col;
            size_t b8 = b0 + 8 * KDIM;
            *reinterpret_cast<uint32_t*>(Aoh + b0) =
                pack_h2(__float2half(y0), __float2half(y1));
            *reinterpret_cast<uint32_t*>(Aoh + b8) =
                pack_h2(__float2half(y2), __float2half(y3));
        }
    }
}

// ---------------------------------------------------------------------------
// Launch
// ---------------------------------------------------------------------------
extern "C" void kernel_launch(void* const* d_in, const int* in_sizes, int n_in,
                              void* d_out, int out_size)
{
    const float *q_embs, *k_embs, *v_embs, *w_q, *w_k, *w_v, *w_o;
    if (in_sizes[3] == D_MODEL * DIM_KV) {
        k_embs = (const float*)d_in[0];
        q_embs = (const float*)d_in[1];
        v_embs = (const float*)d_in[2];
        w_k    = (const float*)d_in[3];
        w_o    = (const float*)d_in[4];
        w_q    = (const float*)d_in[5];
        w_v    = (const float*)d_in[6];
    } else {
        q_embs = (const float*)d_in[0];
        k_embs = (const float*)d_in[1];
        v_embs = (const float*)d_in[2];
        w_q    = (const float*)d_in[3];
        w_k    = (const float*)d_in[4];
        w_v    = (const float*)d_in[5];
        w_o    = (const float*)d_in[6];
    }
    float* out = (float*)d_out;

    float *RC, *RS;
    __half *Ahq, *Ahk, *Ahv, *Aoh, *B2q, *B2k, *B2v, *B2o, *Q2, *K2h, *Vth;
    cudaGetSymbolAddress((void**)&Ahq, g_Ahq);
    cudaGetSymbolAddress((void**)&Ahk, g_Ahk);
    cudaGetSymbolAddress((void**)&Ahv, g_Ahv);
    cudaGetSymbolAddress((void**)&Aoh, g_Aoh);
    cudaGetSymbolAddress((void**)&B2q, g_B2q);
    cudaGetSymbolAddress((void**)&B2k, g_B2k);
    cudaGetSymbolAddress((void**)&B2v, g_B2v);
    cudaGetSymbolAddress((void**)&B2o, g_B2o);
    cudaGetSymbolAddress((void**)&Q2,  g_Q2);
    cudaGetSymbolAddress((void**)&K2h, g_K2h);
    cudaGetSymbolAddress((void**)&Vth, g_Vth);
    cudaGetSymbolAddress((void**)&RC,  g_rc);
    cudaGetSymbolAddress((void**)&RS,  g_rs);

    cudaFuncSetAttribute(gemm_uber_kernel,
                         cudaFuncAttributeMaxDynamicSharedMemorySize, GEMM_SMEM_BYTES);
    cudaFuncSetAttribute(gemm_o_kernel,
                         cudaFuncAttributeMaxDynamicSharedMemorySize, GEMM_SMEM_BYTES);
    cudaFuncSetAttribute(flash_hmma_kernel,
                         cudaFuncAttributeMaxDynamicSharedMemorySize, FLASH_SMEM_BYTES);

    rope_table_kernel<<<(T_SEQ * 32 + 255) / 256, 256>>>(RC, RS);                 // 1
    conv_a3_kernel<<<dim3((T_SEQ * (KDIM / 4) + 255) / 256, 1, 3), 256>>>(
        q_embs, k_embs, v_embs, Ahq, Ahk, Ahv);                                   // 2
    split_b4_kernel<<<dim3(D_MODEL / 32, KDIM / 32, 4), dim3(32, 8)>>>(
        w_q, w_k, w_v, w_o, B2q, B2k, B2v, B2o);                                  // 3

    gemm_uber_kernel<<<384, 128, GEMM_SMEM_BYTES>>>(
        Ahq, B2q, Ahk, B2k, Ahv, B2v, Q2, K2h, Vth, RC, RS);                      // 4 (profile slot)

    flash_hmma_kernel<<<dim3(T_SEQ / 128, NQH), 128, FLASH_SMEM_BYTES>>>(
        Q2, K2h, Vth, Aoh);                                                       // 5

    gemm_o_kernel<<<dim3(D_MODEL / 128, T_SEQ / 128), 128, GEMM_SMEM_BYTES>>>(
        Aoh, B2o, out);                                                           // 6
}

// round 17
// speedup vs baseline: 1.8589x; 1.0996x over previous
#include <cuda_runtime.h>
#include <cuda_bf16.h>
#include <cuda_fp16.h>
#include <math.h>
#include <stdint.h>

#define D_MODEL 2048
#define T_SEQ   2048
#define NQH     32
#define NKVH    8
#define HD      64
#define DIM_KV  512
#define KDIM    2048
#define PADH    72             // GEMM smem row stride (halves)
#define KVPAD   72             // flash Q/K/V smem row stride (halves)

// ---------------------------------------------------------------------------
// Device-global scratch (all attention operands hi-only fp16)
// ---------------------------------------------------------------------------
__device__ __align__(16) __half g_Ahq[T_SEQ * KDIM];
__device__ __align__(16) __half g_Ahk[T_SEQ * KDIM];
__device__ __align__(16) __half g_Ahv[T_SEQ * KDIM];
__device__ __align__(16) __half g_Aoh[T_SEQ * KDIM];     // flash output, hi only
__device__ __align__(16) __half g_B2q[D_MODEL * KDIM];
__device__ __align__(16) __half g_B2k[DIM_KV  * KDIM];
__device__ __align__(16) __half g_B2v[DIM_KV  * KDIM];
__device__ __align__(16) __half g_B2o[D_MODEL * KDIM];
__device__ __align__(16) __half g_Qh[NQH  * T_SEQ * 64];  // [h][t][Qh]
__device__ __align__(16) __half g_K2h[NKVH * T_SEQ * 64]; // [kvh][t][Kh]
__device__ __align__(16) __half g_Vth[DIM_KV * T_SEQ];    // V^T hi [d][t]
__device__ float g_rc[T_SEQ * 32];
__device__ float g_rs[T_SEQ * 32];

// ---------------------------------------------------------------------------
// PTX helpers
// ---------------------------------------------------------------------------
__device__ __forceinline__ uint32_t smem_u32(const void* p) {
    uint32_t a;
    asm("{ .reg .u64 t; cvta.to.shared.u64 t, %1; cvt.u32.u64 %0, t; }"
        : "=r"(a) : "l"(p));
    return a;
}

__device__ __forceinline__ void ldmatrix_x4(uint32_t& r0, uint32_t& r1,
                                            uint32_t& r2, uint32_t& r3,
                                            uint32_t addr) {
    asm volatile("ldmatrix.sync.aligned.m8n8.x4.shared.b16 {%0,%1,%2,%3}, [%4];"
                 : "=r"(r0), "=r"(r1), "=r"(r2), "=r"(r3) : "r"(addr));
}

__device__ __forceinline__ void mma16816(float* d, const uint32_t* a,
                                         uint32_t b0, uint32_t b1) {
    asm volatile(
        "mma.sync.aligned.m16n8k16.row.col.f32.f16.f16.f32 "
        "{%0,%1,%2,%3}, {%4,%5,%6,%7}, {%8,%9}, {%0,%1,%2,%3};"
        : "+f"(d[0]), "+f"(d[1]), "+f"(d[2]), "+f"(d[3])
        : "r"(a[0]), "r"(a[1]), "r"(a[2]), "r"(a[3]), "r"(b0), "r"(b1));
}

__device__ __forceinline__ void cp_async16(uint32_t saddr, const void* gaddr) {
    asm volatile("cp.async.cg.shared.global [%0], [%1], 16;"
                 :: "r"(saddr), "l"(gaddr));
}
#define CP_COMMIT() asm volatile("cp.async.commit_group;" ::: "memory")
#define CP_WAIT(n)  asm volatile("cp.async.wait_group %0;" :: "n"(n) : "memory")

__device__ __forceinline__ uint32_t pack_h2(__half a, __half b) {
    return ((uint32_t)__half_as_ushort(b) << 16) | __half_as_ushort(a);
}

// ---------------------------------------------------------------------------
// Conversions
// ---------------------------------------------------------------------------
__global__ void conv_a3_kernel(const float* __restrict__ Xq,
                               const float* __restrict__ Xk,
                               const float* __restrict__ Xv,
                               __half* __restrict__ Ahq,
                               __half* __restrict__ Ahk,
                               __half* __restrict__ Ahv)
{
    const float* X = (blockIdx.z == 0) ? Xq : (blockIdx.z == 1) ? Xk : Xv;
    __half* A      = (blockIdx.z == 0) ? Ahq : (blockIdx.z == 1) ? Ahk : Ahv;
    int idx = blockIdx.x * blockDim.x + threadIdx.x;
    if (idx >= T_SEQ * (KDIM / 4)) return;
    float4 x = *reinterpret_cast<const float4*>(X + (size_t)idx * 4);
    *reinterpret_cast<uint2*>(A + (size_t)idx * 4) = make_uint2(
        pack_h2(__float2half(x.x), __float2half(x.y)),
        pack_h2(__float2half(x.z), __float2half(x.w)));
}

__global__ void split_b4_kernel(const float* __restrict__ Wq,
                                const float* __restrict__ Wk,
                                const float* __restrict__ Wv,
                                const float* __restrict__ Wo,
                                __half* __restrict__ B2q,
                                __half* __restrict__ B2k,
                                __half* __restrict__ B2v,
                                __half* __restrict__ B2o)
{
    const int z = blockIdx.z;
    const float* W = (z == 0) ? Wq : (z == 1) ? Wk : (z == 2) ? Wv : Wo;
    __half* B2     = (z == 0) ? B2q : (z == 1) ? B2k : (z == 2) ? B2v : B2o;
    const int N    = (z == 1 || z == 2) ? DIM_KV : D_MODEL;

    __shared__ float tile[32][33];
    int n0 = blockIdx.x * 32, k0 = blockIdx.y * 32;
    if (n0 >= N) return;
    int tx = threadIdx.x, ty = threadIdx.y;   // 32 x 8
    #pragma unroll
    for (int i = 0; i < 32; i += 8)
        tile[ty + i][tx] = W[(size_t)(k0 + ty + i) * N + n0 + tx];
    __syncthreads();
    int tid = ty * 32 + tx;
    int nl  = tid >> 3;
    int k4  = (tid & 7) * 4;
    __half h0 = __float2half(tile[k4 + 0][nl]);
    __half h1 = __float2half(tile[k4 + 1][nl]);
    __half h2 = __float2half(tile[k4 + 2][nl]);
    __half h3 = __float2half(tile[k4 + 3][nl]);
    *reinterpret_cast<uint2*>(B2 + (size_t)(n0 + nl) * KDIM + k0 + k4) =
        make_uint2(pack_h2(h0, h1), pack_h2(h2, h3));
}

__global__ void rope_table_kernel(float* __restrict__ rc, float* __restrict__ rs)
{
    int idx = blockIdx.x * blockDim.x + threadIdx.x;
    if (idx >= T_SEQ * 32) return;
    int t = idx >> 5, i = idx & 31;
    float invf = (float)pow(500000.0, -(double)i / 32.0);
    float angf = (float)t * invf;
    double ang = (double)angf;
    rc[idx] = (float)cos(ang);
    rs[idx] = (float)sin(ang);
}

// ---------------------------------------------------------------------------
// Shared GEMM mainloop: A [*,2048] fp16, B [*,2048] fp16, K = 2048 (32 chunks)
// ---------------------------------------------------------------------------
#define GEMM_SMEM_BYTES (4 * 128 * PADH * 2)   // 73728

__device__ __forceinline__ void ldgsts_tileS(uint32_t sBase, const __half* G,
                                             int k0, int tid)
{
    #pragma unroll
    for (int i = 0; i < 8; i++) {
        int id  = tid + (i << 7);
        int row = id >> 3;
        int c8  = id & 7;
        cp_async16(sBase + (uint32_t)(row * PADH + c8 * 8) * 2,
                   G + (size_t)row * KDIM + k0 + c8 * 8);
    }
}

__device__ __forceinline__ void gemm_mainloop(
    uint32_t shBase, const __half* Ag, const __half* Bg,
    int tid, int lane, int wm, int wn, float acc[4][8][4])
{
    const uint32_t TILE_B = 128 * PADH * 2;
    const int nCh = KDIM / 64;   // 32

    ldgsts_tileS(shBase + 0 * TILE_B, Ag, 0, tid);
    ldgsts_tileS(shBase + 2 * TILE_B, Bg, 0, tid);
    CP_COMMIT();

    const int lrow = (lane & 7) + ((lane >> 3) & 1) * 8;
    const int lcol = (lane >> 4) * 8;

    for (int c = 0; c < nCh; c++) {
        const int s = c & 1;
        if (c + 1 < nCh) {
            const int s2 = s ^ 1;
            ldgsts_tileS(shBase + s2 * TILE_B,       Ag, (c + 1) * 64, tid);
            ldgsts_tileS(shBase + (2 + s2) * TILE_B, Bg, (c + 1) * 64, tid);
            CP_COMMIT();
            CP_WAIT(1);
        } else {
            CP_WAIT(0);
        }
        __syncthreads();

        const uint32_t aB = shBase + s * TILE_B;
        const uint32_t bB = shBase + (2 + s) * TILE_B;
        #pragma unroll
        for (int ks = 0; ks < 4; ks++) {
            const int k16 = ks * 16;
            uint32_t af[4][4], bfr[4][4];
            #pragma unroll
            for (int fm = 0; fm < 4; fm++)
                ldmatrix_x4(af[fm][0], af[fm][1], af[fm][2], af[fm][3],
                    aB + (uint32_t)((wm * 64 + fm * 16 + lrow) * PADH + k16 + lcol) * 2);
            #pragma unroll
            for (int fp = 0; fp < 4; fp++)
                ldmatrix_x4(bfr[fp][0], bfr[fp][1], bfr[fp][2], bfr[fp][3],
                    bB + (uint32_t)((wn * 64 + fp * 16 + lrow) * PADH + k16 + lcol) * 2);
            #pragma unroll
            for (int fm = 0; fm < 4; fm++)
                #pragma unroll
                for (int fn = 0; fn < 8; fn++) {
                    uint32_t b0 = (fn & 1) ? bfr[fn >> 1][1] : bfr[fn >> 1][0];
                    uint32_t b1 = (fn & 1) ? bfr[fn >> 1][3] : bfr[fn >> 1][2];
                    mma16816(acc[fm][fn], af[fm], b0, b1);
                }
        }
        __syncthreads();
    }
}

// ---------------------------------------------------------------------------
// Uber projection kernel: Q (256 CTAs) + K (64) + V (64), all hi-only.
// Q and K epilogues: rope -> hi fp16 [h][t][64]. V: transposed hi.
// ---------------------------------------------------------------------------
__global__ __launch_bounds__(128, 2) void gemm_uber_kernel(
    const __half* __restrict__ Ahq, const __half* __restrict__ B2q,
    const __half* __restrict__ Ahk, const __half* __restrict__ B2k,
    const __half* __restrict__ Ahv, const __half* __restrict__ B2v,
    __half* __restrict__ Qh, __half* __restrict__ K2h, __half* __restrict__ Vth,
    const float* __restrict__ rc, const float* __restrict__ rs)
{
    extern __shared__ __half sh[];
    uint32_t shBase = smem_u32(sh);
    const int tid  = threadIdx.x;
    const int lane = tid & 31;
    const int wid  = tid >> 5;
    const int wm   = wid & 1;
    const int wn   = wid >> 1;

    const int bid = blockIdx.x;
    int mode, rowBase, colBase;
    const __half *Ap, *Bp;
    __half* Dst;
    if (bid < 256) {
        mode = 0;
        rowBase = (bid >> 4) * 128;
        colBase = (bid & 15) * 128;
        Ap = Ahq; Bp = B2q; Dst = Qh;
    } else if (bid < 320) {
        mode = 1;
        int b = bid - 256;
        rowBase = (b >> 2) * 128;
        colBase = (b & 3) * 128;
        Ap = Ahk; Bp = B2k; Dst = K2h;
    } else {
        mode = 2;
        int b = bid - 320;
        rowBase = (b >> 2) * 128;
        colBase = (b & 3) * 128;
        Ap = Ahv; Bp = B2v; Dst = Vth;
    }

    float acc[4][8][4];
    #pragma unroll
    for (int i = 0; i < 4; i++)
        #pragma unroll
        for (int j = 0; j < 8; j++)
            #pragma unroll
            for (int q = 0; q < 4; q++) acc[i][j][q] = 0.0f;

    gemm_mainloop(shBase, Ap + (size_t)rowBase * KDIM, Bp + (size_t)colBase * KDIM,
                  tid, lane, wm, wn, acc);

    #pragma unroll
    for (int fm = 0; fm < 4; fm++) {
        #pragma unroll
        for (int fn = 0; fn < 8; fn++) {
            int r0 = rowBase + wm * 64 + fm * 16 + (lane >> 2);
            int c0 = colBase + wn * 64 + fn * 8 + (lane & 3) * 2;
            float a0 = acc[fm][fn][0], a1 = acc[fm][fn][1];
            float a2 = acc[fm][fn][2], a3 = acc[fm][fn][3];
            if (mode == 2) {
                Dst[(size_t)c0 * T_SEQ + r0]           = __float2half(a0);
                Dst[(size_t)(c0 + 1) * T_SEQ + r0]     = __float2half(a1);
                Dst[(size_t)c0 * T_SEQ + r0 + 8]       = __float2half(a2);
                Dst[(size_t)(c0 + 1) * T_SEQ + r0 + 8] = __float2half(a3);
            } else {
                const int h = c0 >> 6;
                const int d = c0 & 63;
                const int i = d >> 1;
                float c1 = rc[r0 * 32 + i],       s1 = rs[r0 * 32 + i];
                float c2 = rc[(r0 + 8) * 32 + i], s2 = rs[(r0 + 8) * 32 + i];
                float y0 = a0 * c1 - a1 * s1, y1 = a0 * s1 + a1 * c1;
                float y2 = a2 * c2 - a3 * s2, y3 = a2 * s2 + a3 * c2;
                size_t b0 = ((size_t)h * T_SEQ + r0) * 64 + d;
                size_t b8 = b0 + 8 * 64;
                *reinterpret_cast<uint32_t*>(Dst + b0) =
                    pack_h2(__float2half(y0), __float2half(y1));
                *reinterpret_cast<uint32_t*>(Dst + b8) =
                    pack_h2(__float2half(y2), __float2half(y3));
            }
        }
    }
}

// O-projection GEMM (hi-only A, K=2048, fp32 store)
__global__ __launch_bounds__(128, 2) void gemm_o_kernel(
    const __half* __restrict__ Aoh, const __half* __restrict__ B2,
    float* __restrict__ C)
{
    extern __shared__ __half sh[];
    uint32_t shBase = smem_u32(sh);
    const int tid  = threadIdx.x;
    const int lane = tid & 31;
    const int wid  = tid >> 5;
    const int wm   = wid & 1;
    const int wn   = wid >> 1;
    const int rowBase = blockIdx.y * 128;
    const int colBase = blockIdx.x * 128;

    float acc[4][8][4];
    #pragma unroll
    for (int i = 0; i < 4; i++)
        #pragma unroll
        for (int j = 0; j < 8; j++)
            #pragma unroll
            for (int q = 0; q < 4; q++) acc[i][j][q] = 0.0f;

    gemm_mainloop(shBase, Aoh + (size_t)rowBase * KDIM, B2 + (size_t)colBase * KDIM,
                  tid, lane, wm, wn, acc);

    #pragma unroll
    for (int fm = 0; fm < 4; fm++) {
        #pragma unroll
        for (int fn = 0; fn < 8; fn++) {
            int r0 = rowBase + wm * 64 + fm * 16 + (lane >> 2);
            int c0 = colBase + wn * 64 + fn * 8 + (lane & 3) * 2;
            *reinterpret_cast<float2*>(&C[(size_t)r0 * D_MODEL + c0]) =
                make_float2(acc[fm][fn][0], acc[fm][fn][1]);
            *reinterpret_cast<float2*>(&C[(size_t)(r0 + 8) * D_MODEL + c0]) =
                make_float2(acc[fm][fn][2], acc[fm][fn][3]);
        }
    }
}

// ---------------------------------------------------------------------------
// HMMA flash attention: all hi-only fp16 operands, fp32 softmax.
// 128 threads, 2 CTAs/SM (smem 36.9KB). Q tile 128x64.
// ---------------------------------------------------------------------------
#define FLASH_SMEM_BYTES ((128 + 64 + 64) * KVPAD * 2)   // 36864

__global__ __launch_bounds__(128, 2) void flash_hmma_kernel(
    const __half* __restrict__ Qh,
    const __half* __restrict__ K2h,
    const __half* __restrict__ Vth,
    __half* __restrict__ Aoh)
{
    extern __shared__ __half fs[];
    const uint32_t QsA = smem_u32(fs);
    const uint32_t KsA = QsA + 128 * KVPAD * 2;
    const uint32_t VsA = KsA + 64 * KVPAD * 2;

    const int tid = threadIdx.x, lane = tid & 31, wq = tid >> 5;
    const int h = blockIdx.y, kvh = h >> 2;
    const int m0 = (gridDim.x - 1 - (int)blockIdx.x) * 128;

    const int g  = lane >> 2;
    const int tg = lane & 3;
    const int lrow = (lane & 7) + ((lane >> 3) & 1) * 8;
    const int lcol = (lane >> 4) * 8;
    const float NEG = -1e30f;
    const float scale = 0.125f;

    {   // Q tile: 128 rows x 64 halves
        const __half* Qg = Qh + ((size_t)h * T_SEQ + m0) * 64;
        #pragma unroll
        for (int u = 0; u < 8; u++) {
            int id = tid + u * 128;
            int row = id >> 3, c = id & 7;
            cp_async16(QsA + (uint32_t)(row * KVPAD + c * 8) * 2,
                       Qg + (size_t)row * 64 + c * 8);
        }
        CP_COMMIT();
    }

    float o[2][8][4];
    #pragma unroll
    for (int i = 0; i < 2; i++)
        #pragma unroll
        for (int j = 0; j < 8; j++)
            #pragma unroll
            for (int q = 0; q < 4; q++) o[i][j][q] = 0.0f;
    float mrow[2][2] = {{NEG, NEG}, {NEG, NEG}};
    float lacc[2][2] = {{0.f, 0.f}, {0.f, 0.f}};

    const int nT = m0 / 64 + 2;
    for (int jt = 0; jt < nT; jt++) {
        const int j0 = jt * 64;
        __syncthreads();
        #pragma unroll
        for (int u = 0; u < 4; u++) {
            int id = tid + u * 128;
            int row = id >> 3, c = id & 7;
            cp_async16(KsA + (uint32_t)(row * KVPAD + c * 8) * 2,
                       K2h + ((size_t)kvh * T_SEQ + j0 + row) * 64 + c * 8);
        }
        #pragma unroll
        for (int u = 0; u < 4; u++) {
            int id = tid + u * 128;
            int row = id >> 3, c = id & 7;
            cp_async16(VsA + (uint32_t)(row * KVPAD + c * 8) * 2,
                       Vth + (size_t)(kvh * 64 + row) * T_SEQ + j0 + c * 8);
        }
        CP_COMMIT();
        CP_WAIT(0);
        __syncthreads();

        // S = Qh·Kh^T (K'=64 -> 4 chunks)
        float s[2][8][4];
        #pragma unroll
        for (int i = 0; i < 2; i++)
            #pragma unroll
            for (int j = 0; j < 8; j++)
                #pragma unroll
                for (int q = 0; q < 4; q++) s[i][j][q] = 0.0f;

        #pragma unroll
        for (int kc = 0; kc < 4; kc++) {
            uint32_t af[2][4], bk[4][4];
            #pragma unroll
            for (int fm = 0; fm < 2; fm++)
                ldmatrix_x4(af[fm][0], af[fm][1], af[fm][2], af[fm][3],
                    QsA + (uint32_t)((wq * 32 + fm * 16 + lrow) * KVPAD + kc * 16 + lcol) * 2);
            #pragma unroll
            for (int fp = 0; fp < 4; fp++)
                ldmatrix_x4(bk[fp][0], bk[fp][1], bk[fp][2], bk[fp][3],
                    KsA + (uint32_t)((fp * 16 + lrow) * KVPAD + kc * 16 + lcol) * 2);
            #pragma unroll
            for (int fm = 0; fm < 2; fm++)
                #pragma unroll
                for (int fn = 0; fn < 8; fn++) {
                    uint32_t b0 = (fn & 1) ? bk[fn >> 1][1] : bk[fn >> 1][0];
                    uint32_t b1 = (fn & 1) ? bk[fn >> 1][3] : bk[fn >> 1][2];
                    mma16816(s[fm][fn], af[fm], b0, b1);
                }
        }

        #pragma unroll
        for (int fm = 0; fm < 2; fm++) {
            const int r0 = m0 + wq * 32 + fm * 16 + g;
            const int r1 = r0 + 8;
            float mx0 = NEG, mx1 = NEG;
            #pragma unroll
            for (int fn = 0; fn < 8; fn++) {
                const int cb = j0 + fn * 8 + tg * 2;
                float v0 = (cb     <= r0) ? s[fm][fn][0] * scale : NEG;
                float v1 = (cb + 1 <= r0) ? s[fm][fn][1] * scale : NEG;
                float v2 = (cb     <= r1) ? s[fm][fn][2] * scale : NEG;
                float v3 = (cb + 1 <= r1) ? s[fm][fn][3] * scale : NEG;
                s[fm][fn][0] = v0; s[fm][fn][1] = v1;
                s[fm][fn][2] = v2; s[fm][fn][3] = v3;
                mx0 = fmaxf(mx0, fmaxf(v0, v1));
                mx1 = fmaxf(mx1, fmaxf(v2, v3));
            }
            mx0 = fmaxf(mx0, __shfl_xor_sync(0xffffffffu, mx0, 1));
            mx0 = fmaxf(mx0, __shfl_xor_sync(0xffffffffu, mx0, 2));
            mx1 = fmaxf(mx1, __shfl_xor_sync(0xffffffffu, mx1, 1));
            mx1 = fmaxf(mx1, __shfl_xor_sync(0xffffffffu, mx1, 2));
            const float mn0 = fmaxf(mrow[fm][0], mx0);
            const float mn1 = fmaxf(mrow[fm][1], mx1);
            const float c0 = __expf(mrow[fm][0] - mn0);
            const float c1 = __expf(mrow[fm][1] - mn1);
            mrow[fm][0] = mn0; mrow[fm][1] = mn1;
            float ls0 = 0.f, ls1 = 0.f;
            #pragma unroll
            for (int fn = 0; fn < 8; fn++) {
                float p0 = __expf(s[fm][fn][0] - mn0);
                float p1 = __expf(s[fm][fn][1] - mn0);
                float p2 = __expf(s[fm][fn][2] - mn1);
                float p3 = __expf(s[fm][fn][3] - mn1);
                s[fm][fn][0] = p0; s[fm][fn][1] = p1;
                s[fm][fn][2] = p2; s[fm][fn][3] = p3;
                ls0 += p0 + p1; ls1 += p2 + p3;
                o[fm][fn][0] *= c0; o[fm][fn][1] *= c0;
                o[fm][fn][2] *= c1; o[fm][fn][3] *= c1;
            }
            lacc[fm][0] = lacc[fm][0] * c0 + ls0;
            lacc[fm][1] = lacc[fm][1] * c1 + ls1;
        }

        // O += Ph·Vh
        #pragma unroll
        for (int kc2 = 0; kc2 < 4; kc2++) {
            uint32_t aPh[2][4];
            #pragma unroll
            for (int fm = 0; fm < 2; fm++) {
                #pragma unroll
                for (int half = 0; half < 2; half++) {
                    const int fr = 2 * kc2 + half;
                    aPh[fm][half * 2 + 0] = pack_h2(
                        __float2half(s[fm][fr][0]), __float2half(s[fm][fr][1]));
                    aPh[fm][half * 2 + 1] = pack_h2(
                        __float2half(s[fm][fr][2]), __float2half(s[fm][fr][3]));
                }
            }
            uint32_t bv[4][4];
            #pragma unroll
            for (int fp = 0; fp < 4; fp++)
                ldmatrix_x4(bv[fp][0], bv[fp][1], bv[fp][2], bv[fp][3],
                    VsA + (uint32_t)((fp * 16 + lrow) * KVPAD + kc2 * 16 + lcol) * 2);
            #pragma unroll
            for (int fm = 0; fm < 2; fm++)
                #pragma unroll
                for (int fn = 0; fn < 8; fn++) {
                    uint32_t b0 = (fn & 1) ? bv[fn >> 1][1] : bv[fn >> 1][0];
                    uint32_t b1 = (fn & 1) ? bv[fn >> 1][3] : bv[fn >> 1][2];
                    mma16816(o[fm][fn], aPh[fm], b0, b1);
                }
        }
    }

    float linv[2][2];
    #pragma unroll
    for (int fm = 0; fm < 2; fm++)
        #pragma unroll
        for (int half = 0; half < 2; half++) {
            float lv = lacc[fm][half];
            lv += __shfl_xor_sync(0xffffffffu, lv, 1);
            lv += __shfl_xor_sync(0xffffffffu, lv, 2);
            linv[fm][half] = 1.0f / lv;
        }
    #pragma unroll
    for (int fm = 0; fm < 2; fm++) {
        const int r0 = m0 + wq * 32 + fm * 16 + g;
        #pragma unroll
        for (int fn = 0; fn < 8; fn++) {
            const int col = h * HD + fn * 8 + tg * 2;
            float y0 = o[fm][fn][0] * linv[fm][0];
            float y1 = o[fm][fn][1] * linv[fm][0];
            float y2 = o[fm][fn][2] * linv[fm][1];
            float y3 = o[fm][fn][3] * linv[fm][1];
            size_t b0 = (size_t)r0 * KDIM + col;
            size_t b8 = b0 + 8 * KDIM;
            *reinterpret_cast<uint32_t*>(Aoh + b0) =
                pack_h2(__float2half(y0), __float2half(y1));
            *reinterpret_cast<uint32_t*>(Aoh + b8) =
                pack_h2(__float2half(y2), __float2half(y3));
        }
    }
}

// ---------------------------------------------------------------------------
// Launch
// ---------------------------------------------------------------------------
extern "C" void kernel_launch(void* const* d_in, const int* in_sizes, int n_in,
                              void* d_out, int out_size)
{
    const float *q_embs, *k_embs, *v_embs, *w_q, *w_k, *w_v, *w_o;
    if (in_sizes[3] == D_MODEL * DIM_KV) {
        k_embs = (const float*)d_in[0];
        q_embs = (const float*)d_in[1];
        v_embs = (const float*)d_in[2];
        w_k    = (const float*)d_in[3];
        w_o    = (const float*)d_in[4];
        w_q    = (const float*)d_in[5];
        w_v    = (const float*)d_in[6];
    } else {
        q_embs = (const float*)d_in[0];
        k_embs = (const float*)d_in[1];
        v_embs = (const float*)d_in[2];
        w_q    = (const float*)d_in[3];
        w_k    = (const float*)d_in[4];
        w_v    = (const float*)d_in[5];
        w_o    = (const float*)d_in[6];
    }
    float* out = (float*)d_out;

    float *RC, *RS;
    __half *Ahq, *Ahk, *Ahv, *Aoh, *B2q, *B2k, *B2v, *B2o, *Qh, *K2h, *Vth;
    cudaGetSymbolAddress((void**)&Ahq, g_Ahq);
    cudaGetSymbolAddress((void**)&Ahk, g_Ahk);
    cudaGetSymbolAddress((void**)&Ahv, g_Ahv);
    cudaGetSymbolAddress((void**)&Aoh, g_Aoh);
    cudaGetSymbolAddress((void**)&B2q, g_B2q);
    cudaGetSymbolAddress((void**)&B2k, g_B2k);
    cudaGetSymbolAddress((void**)&B2v, g_B2v);
    cudaGetSymbolAddress((void**)&B2o, g_B2o);
    cudaGetSymbolAddress((void**)&Qh,  g_Qh);
    cudaGetSymbolAddress((void**)&K2h, g_K2h);
    cudaGetSymbolAddress((void**)&Vth, g_Vth);
    cudaGetSymbolAddress((void**)&RC,  g_rc);
    cudaGetSymbolAddress((void**)&RS,  g_rs);

    cudaFuncSetAttribute(gemm_uber_kernel,
                         cudaFuncAttributeMaxDynamicSharedMemorySize, GEMM_SMEM_BYTES);
    cudaFuncSetAttribute(gemm_o_kernel,
                         cudaFuncAttributeMaxDynamicSharedMemorySize, GEMM_SMEM_BYTES);
    cudaFuncSetAttribute(flash_hmma_kernel,
                         cudaFuncAttributeMaxDynamicSharedMemorySize, FLASH_SMEM_BYTES);

    rope_table_kernel<<<(T_SEQ * 32 + 255) / 256, 256>>>(RC, RS);                 // 1
    conv_a3_kernel<<<dim3((T_SEQ * (KDIM / 4) + 255) / 256, 1, 3), 256>>>(
        q_embs, k_embs, v_embs, Ahq, Ahk, Ahv);                                   // 2
    split_b4_kernel<<<dim3(D_MODEL / 32, KDIM / 32, 4), dim3(32, 8)>>>(
        w_q, w_k, w_v, w_o, B2q, B2k, B2v, B2o);                                  // 3

    gemm_uber_kernel<<<384, 128, GEMM_SMEM_BYTES>>>(
        Ahq, B2q, Ahk, B2k, Ahv, B2v, Qh, K2h, Vth, RC, RS);                      // 4 (profile slot)

    flash_hmma_kernel<<<dim3(T_SEQ / 128, NQH), 128, FLASH_SMEM_BYTES>>>(
        Qh, K2h, Vth, Aoh);                                                       // 5

    gemm_o_kernel<<<dim3(D_MODEL / 128, T_SEQ / 128), 128, GEMM_SMEM_BYTES>>>(
        Aoh, B2o, out);                                                           // 6
}